// round 13
// baseline (speedup 1.0000x reference)
#include <cuda_runtime.h>
#include <cstdint>

#define NU   100000
#define NPC  20000
#define NURL 50000
#define EUP  250000
#define EUU  500000
#define HD   128
#define MAXB 128
#define ASTRIDE 132
#define NB_PC ((NPC + 63) / 64)
#define NB_URL ((NURL + 63) / 64)

// ---------------- scratch ----------------
__device__ __align__(16) float g_mx_pc[NPC*8];    // cols 0..5 sum, 6 count, 7 zero
__device__ __align__(16) float g_mx_url[NURL*8];
__device__ __align__(16) float g_pcH[NPC*64];
__device__ __align__(16) float g_urlH[NURL*64];

// folded weights
__device__ __align__(16) float g_Wf[2*HD*64];     // WfP | WfR
__device__ __align__(16) float g_W2pc[HD*HD];
__device__ __align__(16) float g_W2url[HD*HD];
__device__ __align__(16) float g_A1pc[8*HD];
__device__ __align__(16) float g_A2pc[8*HD];
__device__ __align__(16) float g_A1url[8*HD];
__device__ __align__(16) float g_A2url[8*HD];
__device__ __align__(16) float g_B1pc[4*HD];
__device__ __align__(16) float g_c1pc[HD];
__device__ __align__(16) float g_B1url[4*HD];     // padded to 4 rows (row 3 zero for url)
__device__ __align__(16) float g_c1url[HD];
__device__ __align__(16) float g_AU[6*64];
__device__ __align__(16) float g_cU[64];

// src-side CSR (for gather_cls)
__device__ __align__(16) int g_cnt_ups[NU];  __device__ int g_off_ups[NU+1];  __device__ int g_cur_ups[NU];  __device__ int g_adj_ups[EUP];
__device__ __align__(16) int g_cnt_uus[NU];  __device__ int g_off_uus[NU+1];  __device__ int g_cur_uus[NU];  __device__ int g_adj_uus[EUU];
__device__ int g_part[2*MAXB];

// ---------------- f32x2 helpers ----------------
typedef unsigned long long u64;
__device__ __forceinline__ u64 f2fma(u64 a, u64 b, u64 c) {
    u64 d; asm("fma.rn.f32x2 %0, %1, %2, %3;" : "=l"(d) : "l"(a), "l"(b), "l"(c)); return d;
}
__device__ __forceinline__ u64 f2pack(float x) {
    u64 r; asm("mov.b64 %0, {%1, %1};" : "=l"(r) : "f"(x)); return r;
}
__device__ __forceinline__ void f2unpack(u64 v, float& x, float& y) {
    asm("mov.b64 {%0, %1}, %2;" : "=f"(x), "=f"(y) : "l"(v));
}
__device__ __forceinline__ void red_v4(float* p, float a, float b, float c, float d) {
    asm volatile("red.global.add.v4.f32 [%0], {%1, %2, %3, %4};"
                 :: "l"(p), "f"(a), "f"(b), "f"(c), "f"(d) : "memory");
}

// ---------------- fused edge-parallel mx accumulation ----------------
__global__ void accum2_kernel(const float* __restrict__ xu,
                              const int* __restrict__ up_src, const int* __restrict__ up_dst,
                              const int* __restrict__ uu_src, const int* __restrict__ uu_dst,
                              float* __restrict__ mxp, float* __restrict__ mxu) {
    int i = blockIdx.x * blockDim.x + threadIdx.x;
    int s, d;
    float* mx;
    if (i < EUP) {
        s = up_src[i]; d = up_dst[i]; mx = mxp;
    } else {
        int e = i - EUP;
        if (e >= EUU) return;
        s = uu_src[e]; d = uu_dst[e]; mx = mxu;
    }
    const float2* xr = (const float2*)(xu + s * 6);
    float2 a = xr[0], b = xr[1], c = xr[2];
    float* m = mx + d * 8;
    red_v4(m,     a.x, a.y, b.x, b.y);
    red_v4(m + 4, c.x, c.y, 1.f, 0.f);
}

// ---------------- src-side CSR ----------------
__global__ void count2_kernel(const int* __restrict__ up_src, const int* __restrict__ uu_src,
                              int* cntP, int* cntU) {
    int i = blockIdx.x * blockDim.x + threadIdx.x;
    if (i < EUP) atomicAdd(&cntP[up_src[i]], 1);
    else {
        int e = i - EUP;
        if (e < EUU) atomicAdd(&cntU[uu_src[e]], 1);
    }
}

struct SetDesc { const int* cnt; int* off; int* cur; int n; };

__global__ void scanA_kernel(SetDesc s0, SetDesc s1) {
    SetDesc s = (blockIdx.y == 0) ? s0 : s1;
    int nb = (s.n + 1023) >> 10;
    if ((int)blockIdx.x >= nb) return;
    int tid = threadIdx.x;
    int i = blockIdx.x * 1024 + tid * 4;
    int sum = 0;
    #pragma unroll
    for (int j = 0; j < 4; j++) { int idx = i + j; if (idx < s.n) sum += s.cnt[idx]; }
    #pragma unroll
    for (int o = 16; o > 0; o >>= 1) sum += __shfl_down_sync(0xffffffffu, sum, o);
    __shared__ int ws[8];
    if ((tid & 31) == 0) ws[tid >> 5] = sum;
    __syncthreads();
    if (tid < 8) {
        int v = ws[tid];
        #pragma unroll
        for (int o = 4; o > 0; o >>= 1) v += __shfl_down_sync(0xffu, v, o);
        if (tid == 0) g_part[blockIdx.y * MAXB + blockIdx.x] = v;
    }
}

__global__ void scanB_kernel(SetDesc s0, SetDesc s1) {
    SetDesc s = (blockIdx.x == 0) ? s0 : s1;
    int nb = (s.n + 1023) >> 10;
    int tid = threadIdx.x;
    int v = (tid < nb) ? g_part[blockIdx.x * MAXB + tid] : 0;
    int lane = tid & 31, w = tid >> 5;
    int x = v;
    #pragma unroll
    for (int o = 1; o < 32; o <<= 1) { int y = __shfl_up_sync(0xffffffffu, x, o); if (lane >= o) x += y; }
    __shared__ int wt[4];
    if (lane == 31) wt[w] = x;
    __syncthreads();
    int add = 0;
    for (int j = 0; j < w; j++) add += wt[j];
    int incl = x + add;
    if (tid < nb) g_part[blockIdx.x * MAXB + tid] = incl - v;
    if (tid == 127) s.off[s.n] = incl;
}

__global__ void scanC_kernel(SetDesc s0, SetDesc s1) {
    SetDesc s = (blockIdx.y == 0) ? s0 : s1;
    int nb = (s.n + 1023) >> 10;
    if ((int)blockIdx.x >= nb) return;
    int tid = threadIdx.x;
    int base = g_part[blockIdx.y * MAXB + blockIdx.x];
    int i = blockIdx.x * 1024 + tid * 4;
    int v0 = 0, v1 = 0, v2 = 0, v3 = 0;
    if (i     < s.n) v0 = s.cnt[i];
    if (i + 1 < s.n) v1 = s.cnt[i + 1];
    if (i + 2 < s.n) v2 = s.cnt[i + 2];
    if (i + 3 < s.n) v3 = s.cnt[i + 3];
    int sv = v0 + v1 + v2 + v3;
    int lane = tid & 31, w = tid >> 5;
    int x = sv;
    #pragma unroll
    for (int o = 1; o < 32; o <<= 1) { int y = __shfl_up_sync(0xffffffffu, x, o); if (lane >= o) x += y; }
    __shared__ int wt[8];
    if (lane == 31) wt[w] = x;
    __syncthreads();
    int add = base;
    for (int j = 0; j < w; j++) add += wt[j];
    int e0 = add + x - sv;
    int e1 = e0 + v0, e2 = e1 + v1, e3 = e2 + v2;
    if (i     < s.n) { s.off[i]     = e0; s.cur[i]     = e0; }
    if (i + 1 < s.n) { s.off[i + 1] = e1; s.cur[i + 1] = e1; }
    if (i + 2 < s.n) { s.off[i + 2] = e2; s.cur[i + 2] = e2; }
    if (i + 3 < s.n) { s.off[i + 3] = e3; s.cur[i + 3] = e3; }
}

__global__ void fill2_kernel(const int* __restrict__ up_src, const int* __restrict__ up_dst,
                             const int* __restrict__ uu_src, const int* __restrict__ uu_dst,
                             int* curP, int* adjP, int* curU, int* adjU) {
    int i = blockIdx.x * blockDim.x + threadIdx.x;
    if (i < EUP) {
        adjP[atomicAdd(&curP[up_src[i]], 1)] = up_dst[i];
    } else {
        int e = i - EUP;
        if (e < EUU) adjU[atomicAdd(&curU[uu_src[e]], 1)] = uu_dst[e];
    }
}

// ---------------- prep: fold all weights (single kernel, 73 blocks) ----------------
__global__ void prep_kernel(const float* __restrict__ Wctx, const float* __restrict__ Wc1,
                            const float* __restrict__ Wu, const float* __restrict__ bu,
                            const float* __restrict__ Wp, const float* __restrict__ bp,
                            const float* __restrict__ Wrf, const float* __restrict__ brf,
                            const float* __restrict__ Wl_pc, const float* __restrict__ Wr_pc,
                            const float* __restrict__ bl_pc,
                            const float* __restrict__ Wl_url, const float* __restrict__ Wr_url,
                            const float* __restrict__ bl_url,
                            const float* __restrict__ bctx, const float* __restrict__ bc1,
                            float* __restrict__ Wf, float* __restrict__ W2pc, float* __restrict__ W2url,
                            float* __restrict__ A1pc, float* __restrict__ A2pc,
                            float* __restrict__ A1url, float* __restrict__ A2url,
                            float* __restrict__ B1pc, float* __restrict__ c1pc,
                            float* __restrict__ B1url, float* __restrict__ c1url,
                            float* __restrict__ AU, float* __restrict__ cU)
{
    int b = blockIdx.x;
    int tid = threadIdx.x;                       // 256
    if (b < 64) {
        __shared__ float sWc1[HD * 64];
        for (int i = tid; i < HD * 64; i += 256) sWc1[i] = Wc1[i];
        __syncthreads();
        int seg = 1 + (b >> 5);
        int r = (b & 31) * 4 + (tid >> 6);
        int c = tid & 63;
        int j = seg * HD + r;
        float acc = 0.f;
        #pragma unroll 8
        for (int m = 0; m < HD; m++) acc = fmaf(Wctx[j * HD + m], sWc1[m * 64 + c], acc);
        Wf[((seg - 1) * HD + r) * 64 + c] = acc;
        return;
    }
    if (b == 64 || b == 65) {
        const float* Wr1 = (b == 64) ? (Wr_pc + HD * HD) : (Wr_url + HD * HD);
        float* W2 = (b == 64) ? W2pc : W2url;
        for (int i = tid; i < HD * HD; i += 256) {
            float v = Wr1[i];
            if ((i >> 7) == (i & 127)) v += 1.f;
            W2[i] = v;
        }
        return;
    }
    if (b >= 66 && b <= 69) {
        const float* Wl;
        float* A;
        if (b == 66)      { Wl = Wl_pc;            A = A1pc; }
        else if (b == 67) { Wl = Wl_pc + HD * HD;  A = A2pc; }
        else if (b == 68) { Wl = Wl_url;           A = A1url; }
        else              { Wl = Wl_url + HD * HD; A = A2url; }
        #pragma unroll
        for (int q = 0; q < 4; q++) {
            int idx = q * 256 + tid;
            int r = idx >> 7, c = idx & 127;
            float acc = 0.f;
            if (r < 6) {
                #pragma unroll 8
                for (int m = 0; m < HD; m++) acc = fmaf(Wu[r * HD + m], Wl[m * HD + c], acc);
            } else if (r == 6) {
                #pragma unroll 8
                for (int m = 0; m < HD; m++) acc = fmaf(bu[m], Wl[m * HD + c], acc);
            }
            A[idx] = acc;
        }
        return;
    }
    if (b == 70 || b == 71) {
        const float* Wsrc = (b == 70) ? Wp : Wrf;
        const float* bsrc = (b == 70) ? bp : brf;
        const float* Wr0  = (b == 70) ? Wr_pc : Wr_url;
        const float* bl0  = (b == 70) ? bl_pc : bl_url;
        float* B1 = (b == 70) ? B1pc : B1url;
        float* c1 = (b == 70) ? c1pc : c1url;
        int Kin = (b == 70) ? 4 : 3;
        int nB = Kin * HD;
        for (int idx = tid; idx < 4 * HD + HD; idx += 256) {
            if (idx < nB) {
                int r = idx / HD, c = idx % HD;
                float acc = 0.f;
                #pragma unroll 8
                for (int m = 0; m < HD; m++) acc = fmaf(Wsrc[r * HD + m], Wr0[m * HD + c], acc);
                B1[idx] = acc;
            } else if (idx < 4 * HD) {
                B1[idx] = 0.f;                        // pad row(s) zero
            } else {
                int c = idx - 4 * HD;
                float acc = bl0[c];
                #pragma unroll 8
                for (int m = 0; m < HD; m++) acc = fmaf(bsrc[m], Wr0[m * HD + c], acc);
                c1[c] = acc;
            }
        }
        return;
    }
    // b == 72: AU = (Wu @ Wctx_U) @ Wc1 ; cU = (bu@Wctx_U + bctx)@Wc1 + bc1
    {
        __shared__ float tmp[7 * HD];
        for (int idx = tid; idx < 7 * HD; idx += 256) {
            int j = idx >> 7, m = idx & 127;
            float acc = 0.f;
            if (j < 6) {
                #pragma unroll 8
                for (int r = 0; r < HD; r++) acc = fmaf(Wu[j * HD + r], Wctx[r * HD + m], acc);
            } else {
                acc = bctx[m];
                #pragma unroll 8
                for (int r = 0; r < HD; r++) acc = fmaf(bu[r], Wctx[r * HD + m], acc);
            }
            tmp[idx] = acc;
        }
        __syncthreads();
        for (int idx = tid; idx < 7 * 64; idx += 256) {
            int j = idx / 64, c = idx % 64;
            float acc = (j == 6) ? bc1[c] : 0.f;
            #pragma unroll 8
            for (int m = 0; m < HD; m++) acc = fmaf(tmp[j * HD + m], Wc1[m * 64 + c], acc);
            if (j < 6) AU[j * 64 + c] = acc;
            else       cU[c] = acc;
        }
    }
}

// ---------------- combined SAGE chain: one launch covers pc + url ----------------
struct SageArgs {
    const float* xf; const float* mx;
    const float* A1; const float* B1; const float* c1;
    const float* A2; const float* W2; const float* c2;
    const float* Wf64; float* outH; int N;
};

__global__ void __launch_bounds__(256, 3) sage_fused(SageArgs pa, SageArgs ua) {
    extern __shared__ float smem[];
    float* T   = smem;                      // [64][ASTRIDE]
    float* sA1 = T + 64 * ASTRIDE;          // 1024
    float* sA2 = sA1 + 8 * HD;              // 1024
    float* sB1 = sA2 + 8 * HD;              // 512 (4 rows, padded)
    float* sc1 = sB1 + 4 * HD;              // 128
    float* sc2 = sc1 + HD;                  // 128
    float* smx = sc2 + HD;                  // 64*8
    float* sxf = smx + 64 * 8;              // 64*4

    const int tid = threadIdx.x;
    const int cq = tid & 15;
    const int rg = tid >> 4;
    const bool isPC = (blockIdx.x < NB_PC);
    const SageArgs a = isPC ? pa : ua;
    const int Kin = isPC ? 4 : 3;
    const int row0 = (isPC ? (int)blockIdx.x : (int)blockIdx.x - NB_PC) * 64;
    const int N = a.N;

    // ---- stage (vectorized; disjoint regions) ----
    ((float4*)sA1)[tid] = ((const float4*)a.A1)[tid];      // 1024 floats
    ((float4*)sA2)[tid] = ((const float4*)a.A2)[tid];
    if (tid < 128) {
        ((float4*)sB1)[tid] = ((const float4*)a.B1)[tid];  // 512 floats (padded rows)
        sc1[tid] = a.c1[tid];
        sc2[tid] = a.c2[tid];
    }
    if (tid < 64) {                                        // one mx row each, normalized
        int gr = row0 + tid;
        float4 m0 = make_float4(0.f, 0.f, 0.f, 0.f);
        float4 m1 = make_float4(0.f, 0.f, 0.f, 0.f);
        if (gr < N) {
            m0 = ((const float4*)a.mx)[gr * 2];
            m1 = ((const float4*)a.mx)[gr * 2 + 1];
        }
        float cnt = m1.z;
        float inv = (cnt > 0.f) ? (1.f / cnt) : 0.f;
        m0.x *= inv; m0.y *= inv; m0.z *= inv; m0.w *= inv;
        m1.x *= inv; m1.y *= inv;
        m1.z = (cnt > 0.f) ? 1.f : 0.f;
        m1.w = 0.f;
        ((float4*)smx)[tid * 2]     = m0;
        ((float4*)smx)[tid * 2 + 1] = m1;
    }
    {                                                      // sxf: 64 rows x 4 (padded) = 256 entries
        int r = tid >> 2, j = tid & 3;
        int gr = row0 + r;
        sxf[tid] = (gr < N && j < Kin) ? a.xf[gr * Kin + j] : 0.f;
    }
    __syncthreads();

    // ---- step1: T = relu(mx@A1 + xf@B1(4 padded rows) + c1) ----
    #pragma unroll
    for (int i = 0; i < 4; i++) {
        int r = rg + i * 16;
        float m[8];
        #pragma unroll
        for (int j = 0; j < 8; j++) m[j] = smx[r * 8 + j];
        float xr[4];
        #pragma unroll
        for (int j = 0; j < 4; j++) xr[j] = sxf[r * 4 + j];
        float o[8];
        #pragma unroll
        for (int jj = 0; jj < 8; jj++) {
            int c = cq * 8 + jj;
            float v = sc1[c];
            #pragma unroll
            for (int j = 0; j < 8; j++) v = fmaf(m[j], sA1[j * HD + c], v);
            #pragma unroll
            for (int j = 0; j < 4; j++) v = fmaf(xr[j], sB1[j * HD + c], v);
            o[jj] = fmaxf(v, 0.f);
        }
        float* tr = &T[r * ASTRIDE + cq * 8];
        #pragma unroll
        for (int p = 0; p < 4; p++) *(float2*)(tr + p * 2) = make_float2(o[2*p], o[2*p+1]);
    }
    __syncthreads();

    // ---- step2: acc = T@W2 (regs), then T <- relu(acc + mx@A2 + c2) ----
    {
        const ulonglong2* W2v = (const ulonglong2*)a.W2;
        u64 acc[4][4];
        #pragma unroll
        for (int i = 0; i < 4; i++)
            #pragma unroll
            for (int p = 0; p < 4; p++) acc[i][p] = 0ULL;
        #pragma unroll 2
        for (int k = 0; k < 128; k += 2) {
            ulonglong2 w10a = W2v[k * 32 + cq * 2];
            ulonglong2 w10b = W2v[k * 32 + cq * 2 + 1];
            ulonglong2 w11a = W2v[(k + 1) * 32 + cq * 2];
            ulonglong2 w11b = W2v[(k + 1) * 32 + cq * 2 + 1];
            #pragma unroll
            for (int i = 0; i < 4; i++) {
                float2 a2 = *(const float2*)&T[(rg + i * 16) * ASTRIDE + k];
                u64 aa0 = f2pack(a2.x), aa1 = f2pack(a2.y);
                acc[i][0] = f2fma(aa0, w10a.x, acc[i][0]);
                acc[i][1] = f2fma(aa0, w10a.y, acc[i][1]);
                acc[i][2] = f2fma(aa0, w10b.x, acc[i][2]);
                acc[i][3] = f2fma(aa0, w10b.y, acc[i][3]);
                acc[i][0] = f2fma(aa1, w11a.x, acc[i][0]);
                acc[i][1] = f2fma(aa1, w11a.y, acc[i][1]);
                acc[i][2] = f2fma(aa1, w11b.x, acc[i][2]);
                acc[i][3] = f2fma(aa1, w11b.y, acc[i][3]);
            }
        }
        __syncthreads();   // all T reads complete before overwrite
        #pragma unroll
        for (int i = 0; i < 4; i++) {
            int r = rg + i * 16;
            float o[8];
            f2unpack(acc[i][0], o[0], o[1]);
            f2unpack(acc[i][1], o[2], o[3]);
            f2unpack(acc[i][2], o[4], o[5]);
            f2unpack(acc[i][3], o[6], o[7]);
            float m[8];
            #pragma unroll
            for (int j = 0; j < 8; j++) m[j] = smx[r * 8 + j];
            #pragma unroll
            for (int jj = 0; jj < 8; jj++) {
                int c = cq * 8 + jj;
                float v = o[jj] + sc2[c];
                #pragma unroll
                for (int j = 0; j < 8; j++) v = fmaf(m[j], sA2[j * HD + c], v);
                o[jj] = fmaxf(v, 0.f);
            }
            float* tr = &T[r * ASTRIDE + cq * 8];
            #pragma unroll
            for (int p = 0; p < 4; p++) *(float2*)(tr + p * 2) = make_float2(o[2*p], o[2*p+1]);
        }
    }
    __syncthreads();

    // ---- step3: outH = T @ Wf64 ----
    {
        const ulonglong2* Wv = (const ulonglong2*)a.Wf64;
        u64 acc[4][2];
        #pragma unroll
        for (int i = 0; i < 4; i++) { acc[i][0] = 0ULL; acc[i][1] = 0ULL; }
        #pragma unroll 2
        for (int k = 0; k < 128; k += 2) {
            ulonglong2 wA = Wv[k * 16 + cq];
            ulonglong2 wB = Wv[(k + 1) * 16 + cq];
            #pragma unroll
            for (int i = 0; i < 4; i++) {
                float2 a2 = *(const float2*)&T[(rg + i * 16) * ASTRIDE + k];
                u64 aa0 = f2pack(a2.x), aa1 = f2pack(a2.y);
                acc[i][0] = f2fma(aa0, wA.x, acc[i][0]);
                acc[i][1] = f2fma(aa0, wA.y, acc[i][1]);
                acc[i][0] = f2fma(aa1, wB.x, acc[i][0]);
                acc[i][1] = f2fma(aa1, wB.y, acc[i][1]);
            }
        }
        const int c0 = cq * 4;
        #pragma unroll
        for (int i = 0; i < 4; i++) {
            int gr = row0 + rg + i * 16;
            if (gr >= N) continue;
            float o[4];
            f2unpack(acc[i][0], o[0], o[1]);
            f2unpack(acc[i][1], o[2], o[3]);
            *(float4*)(a.outH + gr * 64 + c0) = make_float4(o[0], o[1], o[2], o[3]);
        }
    }
}

// ---------------- fused gather + user-term + classifier: 1 warp/user ----------------
__global__ void __launch_bounds__(256) gather_cls_kernel(
    const float* __restrict__ xu, const float* __restrict__ AU, const float* __restrict__ cU,
    const float* __restrict__ pcH, const float* __restrict__ urlH,
    const int* __restrict__ offP, const int* __restrict__ adjP,
    const int* __restrict__ offR, const int* __restrict__ adjR,
    const float* __restrict__ Wc2, const float* __restrict__ bc2,
    float* __restrict__ out, int N)
{
    __shared__ float sAU[6 * 64];
    __shared__ float scU[64];
    __shared__ float sW2[128];
    int tid = threadIdx.x;                    // 256 = 8 warps = 8 users
    for (int i = tid; i < 384; i += 256) sAU[i] = AU[i];
    if (tid < 64) scU[tid] = cU[tid];
    if (tid >= 64 && tid < 192) sW2[tid - 64] = Wc2[tid - 64];
    __syncthreads();

    int w = tid >> 5, lane = tid & 31;
    int u = blockIdx.x * 8 + w;
    if (u >= N) return;
    int c0 = lane * 2;

    float a0 = scU[c0], a1 = scU[c0 + 1];
    #pragma unroll
    for (int j = 0; j < 6; j++) {
        float xv = __ldg(&xu[u * 6 + j]);
        a0 = fmaf(xv, sAU[j * 64 + c0], a0);
        a1 = fmaf(xv, sAU[j * 64 + c0 + 1], a1);
    }
    {
        int e = offP[u], end = offP[u + 1];
        for (; e + 2 <= end; e += 2) {
            int i0 = adjP[e], i1 = adjP[e + 1];
            float2 v0 = *(const float2*)&pcH[i0 * 64 + c0];
            float2 v1 = *(const float2*)&pcH[i1 * 64 + c0];
            a0 += v0.x + v1.x;
            a1 += v0.y + v1.y;
        }
        if (e < end) {
            float2 v = *(const float2*)&pcH[adjP[e] * 64 + c0];
            a0 += v.x; a1 += v.y;
        }
    }
    {
        int e = offR[u], end = offR[u + 1];
        for (; e + 4 <= end; e += 4) {
            int i0 = adjR[e], i1 = adjR[e + 1], i2 = adjR[e + 2], i3 = adjR[e + 3];
            float2 v0 = *(const float2*)&urlH[i0 * 64 + c0];
            float2 v1 = *(const float2*)&urlH[i1 * 64 + c0];
            float2 v2 = *(const float2*)&urlH[i2 * 64 + c0];
            float2 v3 = *(const float2*)&urlH[i3 * 64 + c0];
            a0 += (v0.x + v1.x) + (v2.x + v3.x);
            a1 += (v0.y + v1.y) + (v2.y + v3.y);
        }
        for (; e < end; e++) {
            float2 v = *(const float2*)&urlH[adjR[e] * 64 + c0];
            a0 += v.x; a1 += v.y;
        }
    }
    float h0 = fmaxf(a0, 0.f), h1 = fmaxf(a1, 0.f);
    float p0 = fmaf(h0, sW2[c0 * 2],     h1 * sW2[(c0 + 1) * 2]);
    float p1 = fmaf(h0, sW2[c0 * 2 + 1], h1 * sW2[(c0 + 1) * 2 + 1]);
    #pragma unroll
    for (int o = 16; o > 0; o >>= 1) {
        p0 += __shfl_down_sync(0xffffffffu, p0, o);
        p1 += __shfl_down_sync(0xffffffffu, p1, o);
    }
    if (lane == 0) {
        out[u * 2 + 0] = p0 + bc2[0];
        out[u * 2 + 1] = p1 + bc2[1];
    }
}

// ---------------- streams/events (static init) ----------------
struct StreamCtx {
    cudaStream_t s1, s2, s3;
    cudaEvent_t evRoot, evPrep, evSage;
    StreamCtx() {
        cudaStreamCreateWithFlags(&s1, cudaStreamNonBlocking);
        cudaStreamCreateWithFlags(&s2, cudaStreamNonBlocking);
        cudaStreamCreateWithFlags(&s3, cudaStreamNonBlocking);
        cudaEventCreateWithFlags(&evRoot, cudaEventDisableTiming);
        cudaEventCreateWithFlags(&evPrep, cudaEventDisableTiming);
        cudaEventCreateWithFlags(&evSage, cudaEventDisableTiming);
    }
};
static StreamCtx g_sc;

// ---------------- host orchestration ----------------
#define SYMADDR(p, s) do { void* _t; cudaGetSymbolAddress(&_t, s); p = (decltype(p))_t; } while (0)

extern "C" void kernel_launch(void* const* d_in, const int* in_sizes, int n_in,
                              void* d_out, int out_size) {
    const float* x_user = (const float*)d_in[0];
    const float* x_pc   = (const float*)d_in[1];
    const float* x_url  = (const float*)d_in[2];
    const int* up_src   = (const int*)d_in[3];
    const int* up_dst   = (const int*)d_in[4];
    const int* uu_src   = (const int*)d_in[5];
    const int* uu_dst   = (const int*)d_in[6];
    const float* Wu = (const float*)d_in[7];
    const float* bu = (const float*)d_in[8];
    const float* Wp = (const float*)d_in[9];
    const float* bp = (const float*)d_in[10];
    const float* Wrf = (const float*)d_in[11];
    const float* brf = (const float*)d_in[12];
    const float* Wl_pc = (const float*)d_in[13];
    const float* bl_pc = (const float*)d_in[14];
    const float* Wr_pc = (const float*)d_in[15];
    const float* Wl_url = (const float*)d_in[16];
    const float* bl_url = (const float*)d_in[17];
    const float* Wr_url = (const float*)d_in[18];
    const float* Wctx = (const float*)d_in[19];
    const float* bctx = (const float*)d_in[20];
    const float* Wc1 = (const float*)d_in[21];
    const float* bc1 = (const float*)d_in[22];
    const float* Wc2 = (const float*)d_in[23];
    const float* bc2 = (const float*)d_in[24];
    float* out = (float*)d_out;

    float *mx_pc, *mx_url, *pcH, *urlH;
    float *Wf, *W2pc, *W2url, *A1pc, *A2pc, *A1url, *A2url, *B1pc, *c1pc, *B1url, *c1url, *AU, *cU;
    SYMADDR(mx_pc, g_mx_pc); SYMADDR(mx_url, g_mx_url);
    SYMADDR(pcH, g_pcH); SYMADDR(urlH, g_urlH);
    SYMADDR(Wf, g_Wf); SYMADDR(W2pc, g_W2pc); SYMADDR(W2url, g_W2url);
    SYMADDR(A1pc, g_A1pc); SYMADDR(A2pc, g_A2pc); SYMADDR(A1url, g_A1url); SYMADDR(A2url, g_A2url);
    SYMADDR(B1pc, g_B1pc); SYMADDR(c1pc, g_c1pc); SYMADDR(B1url, g_B1url); SYMADDR(c1url, g_c1url);
    SYMADDR(AU, g_AU); SYMADDR(cU, g_cU);

    int *cnt_ups, *off_ups, *cur_ups, *adj_ups;
    int *cnt_uus, *off_uus, *cur_uus, *adj_uus;
    SYMADDR(cnt_ups, g_cnt_ups); SYMADDR(off_ups, g_off_ups); SYMADDR(cur_ups, g_cur_ups); SYMADDR(adj_ups, g_adj_ups);
    SYMADDR(cnt_uus, g_cnt_uus); SYMADDR(off_uus, g_off_uus); SYMADDR(cur_uus, g_cur_uus); SYMADDR(adj_uus, g_adj_uus);

    const int SAGE_SMEM = (64 * ASTRIDE + 8 * HD * 2 + 4 * HD + 2 * HD + 64 * 8 + 64 * 4) * 4;  // 48128 B
    cudaFuncSetAttribute(sage_fused, cudaFuncAttributeMaxDynamicSharedMemorySize, SAGE_SMEM);

    cudaStream_t s0 = 0;
    cudaStream_t s2 = g_sc.s2, s3 = g_sc.s3;

    // ---- fork ----
    cudaEventRecord(g_sc.evRoot, s0);
    cudaStreamWaitEvent(s2, g_sc.evRoot, 0);
    cudaStreamWaitEvent(s3, g_sc.evRoot, 0);

    // ---- s3: weight folding ----
    prep_kernel<<<73, 256, 0, s3>>>(Wctx, Wc1, Wu, bu, Wp, bp, Wrf, brf,
                                    Wl_pc, Wr_pc, bl_pc, Wl_url, Wr_url, bl_url,
                                    bctx, bc1,
                                    Wf, W2pc, W2url, A1pc, A2pc, A1url, A2url,
                                    B1pc, c1pc, B1url, c1url, AU, cU);
    cudaEventRecord(g_sc.evPrep, s3);

    // ---- s2: zero mx + fused accumulation + combined SAGE (single launch) ----
    cudaMemsetAsync(mx_url, 0, NURL * 8 * sizeof(float), s2);
    cudaMemsetAsync(mx_pc, 0, NPC * 8 * sizeof(float), s2);
    accum2_kernel<<<(EUP + EUU + 255) / 256, 256, 0, s2>>>(x_user, up_src, up_dst,
                                                           uu_src, uu_dst, mx_pc, mx_url);
    cudaStreamWaitEvent(s2, g_sc.evPrep, 0);
    SageArgs pa{x_pc,  mx_pc,  A1pc,  B1pc,  c1pc,  A2pc,  W2pc,  bl_pc + HD,  Wf,           pcH,  NPC};
    SageArgs ua{x_url, mx_url, A1url, B1url, c1url, A2url, W2url, bl_url + HD, Wf + HD * 64, urlH, NURL};
    sage_fused<<<NB_PC + NB_URL, 256, SAGE_SMEM, s2>>>(pa, ua);
    cudaEventRecord(g_sc.evSage, s2);

    // ---- s0: src-side CSR (overlapped) ----
    cudaMemsetAsync(cnt_ups, 0, NU * sizeof(int), s0);
    cudaMemsetAsync(cnt_uus, 0, NU * sizeof(int), s0);
    count2_kernel<<<(EUP + EUU + 255) / 256, 256, 0, s0>>>(up_src, uu_src, cnt_ups, cnt_uus);
    SetDesc d2{cnt_ups, off_ups, cur_ups, NU};
    SetDesc d3{cnt_uus, off_uus, cur_uus, NU};
    dim3 gScan((NU + 1023) / 1024, 2);
    scanA_kernel<<<gScan, 256, 0, s0>>>(d2, d3);
    scanB_kernel<<<2, 128, 0, s0>>>(d2, d3);
    scanC_kernel<<<gScan, 256, 0, s0>>>(d2, d3);
    fill2_kernel<<<(EUP + EUU + 255) / 256, 256, 0, s0>>>(up_src, up_dst, uu_src, uu_dst,
                                                          cur_ups, adj_ups, cur_uus, adj_uus);

    // ---- join on s0: fused gather + classifier ----
    cudaStreamWaitEvent(s0, g_sc.evSage, 0);
    gather_cls_kernel<<<(NU + 7) / 8, 256, 0, s0>>>(x_user, AU, cU, pcH, urlH,
                                                    off_ups, adj_ups, off_uus, adj_uus,
                                                    Wc2, bc2, out, NU);
}

// round 14
// speedup vs baseline: 1.0358x; 1.0358x over previous
#include <cuda_runtime.h>
#include <cstdint>

#define NU   100000
#define NPC  20000
#define NURL 50000
#define EUP  250000
#define EUU  500000
#define HD   128
#define MAXB 128
#define ASTRIDE 132

// ---------------- scratch ----------------
__device__ __align__(16) float g_mx_pc[NPC*8];    // cols 0..5 sum, 6 count, 7 zero
__device__ __align__(16) float g_mx_url[NURL*8];
__device__ __align__(16) float g_pcH[NPC*64];
__device__ __align__(16) float g_urlH[NURL*64];

// folded weights
__device__ __align__(16) float g_Wf[2*HD*64];     // WfP | WfR
__device__ __align__(16) float g_W2pc[HD*HD];
__device__ __align__(16) float g_W2url[HD*HD];
__device__ __align__(16) float g_A1pc[8*HD];
__device__ __align__(16) float g_A2pc[8*HD];
__device__ __align__(16) float g_A1url[8*HD];
__device__ __align__(16) float g_A2url[8*HD];
__device__ __align__(16) float g_B1pc[4*HD];
__device__ __align__(16) float g_c1pc[HD];
__device__ __align__(16) float g_B1url[4*HD];     // padded to 4 rows (row 3 zero for url)
__device__ __align__(16) float g_c1url[HD];
__device__ __align__(16) float g_AU[6*64];
__device__ __align__(16) float g_cU[64];

// src-side CSR (for gather_cls)
__device__ __align__(16) int g_cnt_ups[NU];  __device__ int g_off_ups[NU+1];  __device__ int g_cur_ups[NU];  __device__ int g_adj_ups[EUP];
__device__ __align__(16) int g_cnt_uus[NU];  __device__ int g_off_uus[NU+1];  __device__ int g_cur_uus[NU];  __device__ int g_adj_uus[EUU];
__device__ int g_part[2*MAXB];

// ---------------- f32x2 helpers ----------------
typedef unsigned long long u64;
__device__ __forceinline__ u64 f2fma(u64 a, u64 b, u64 c) {
    u64 d; asm("fma.rn.f32x2 %0, %1, %2, %3;" : "=l"(d) : "l"(a), "l"(b), "l"(c)); return d;
}
__device__ __forceinline__ u64 f2pack(float x) {
    u64 r; asm("mov.b64 %0, {%1, %1};" : "=l"(r) : "f"(x)); return r;
}
__device__ __forceinline__ void f2unpack(u64 v, float& x, float& y) {
    asm("mov.b64 {%0, %1}, %2;" : "=f"(x), "=f"(y) : "l"(v));
}
__device__ __forceinline__ void red_v4(float* p, float a, float b, float c, float d) {
    asm volatile("red.global.add.v4.f32 [%0], {%1, %2, %3, %4};"
                 :: "l"(p), "f"(a), "f"(b), "f"(c), "f"(d) : "memory");
}

// ---------------- per-type edge-parallel mx accumulation ----------------
__global__ void accum_kernel(const float* __restrict__ xu,
                             const int* __restrict__ src, const int* __restrict__ dst,
                             int E, float* __restrict__ mx) {
    int i = blockIdx.x * blockDim.x + threadIdx.x;
    if (i >= E) return;
    int s = src[i], d = dst[i];
    const float2* xr = (const float2*)(xu + s * 6);
    float2 a = xr[0], b = xr[1], c = xr[2];
    float* m = mx + d * 8;
    red_v4(m,     a.x, a.y, b.x, b.y);
    red_v4(m + 4, c.x, c.y, 1.f, 0.f);
}

// ---------------- src-side CSR ----------------
__global__ void count2_kernel(const int* __restrict__ up_src, const int* __restrict__ uu_src,
                              int* cntP, int* cntU) {
    int i = blockIdx.x * blockDim.x + threadIdx.x;
    if (i < EUP) atomicAdd(&cntP[up_src[i]], 1);
    else {
        int e = i - EUP;
        if (e < EUU) atomicAdd(&cntU[uu_src[e]], 1);
    }
}

struct SetDesc { const int* cnt; int* off; int* cur; int n; };

__global__ void scanA_kernel(SetDesc s0, SetDesc s1) {
    SetDesc s = (blockIdx.y == 0) ? s0 : s1;
    int nb = (s.n + 1023) >> 10;
    if ((int)blockIdx.x >= nb) return;
    int tid = threadIdx.x;
    int i = blockIdx.x * 1024 + tid * 4;
    int sum = 0;
    #pragma unroll
    for (int j = 0; j < 4; j++) { int idx = i + j; if (idx < s.n) sum += s.cnt[idx]; }
    #pragma unroll
    for (int o = 16; o > 0; o >>= 1) sum += __shfl_down_sync(0xffffffffu, sum, o);
    __shared__ int ws[8];
    if ((tid & 31) == 0) ws[tid >> 5] = sum;
    __syncthreads();
    if (tid < 8) {
        int v = ws[tid];
        #pragma unroll
        for (int o = 4; o > 0; o >>= 1) v += __shfl_down_sync(0xffu, v, o);
        if (tid == 0) g_part[blockIdx.y * MAXB + blockIdx.x] = v;
    }
}

__global__ void scanB_kernel(SetDesc s0, SetDesc s1) {
    SetDesc s = (blockIdx.x == 0) ? s0 : s1;
    int nb = (s.n + 1023) >> 10;
    int tid = threadIdx.x;
    int v = (tid < nb) ? g_part[blockIdx.x * MAXB + tid] : 0;
    int lane = tid & 31, w = tid >> 5;
    int x = v;
    #pragma unroll
    for (int o = 1; o < 32; o <<= 1) { int y = __shfl_up_sync(0xffffffffu, x, o); if (lane >= o) x += y; }
    __shared__ int wt[4];
    if (lane == 31) wt[w] = x;
    __syncthreads();
    int add = 0;
    for (int j = 0; j < w; j++) add += wt[j];
    int incl = x + add;
    if (tid < nb) g_part[blockIdx.x * MAXB + tid] = incl - v;
    if (tid == 127) s.off[s.n] = incl;
}

__global__ void scanC_kernel(SetDesc s0, SetDesc s1) {
    SetDesc s = (blockIdx.y == 0) ? s0 : s1;
    int nb = (s.n + 1023) >> 10;
    if ((int)blockIdx.x >= nb) return;
    int tid = threadIdx.x;
    int base = g_part[blockIdx.y * MAXB + blockIdx.x];
    int i = blockIdx.x * 1024 + tid * 4;
    int v0 = 0, v1 = 0, v2 = 0, v3 = 0;
    if (i     < s.n) v0 = s.cnt[i];
    if (i + 1 < s.n) v1 = s.cnt[i + 1];
    if (i + 2 < s.n) v2 = s.cnt[i + 2];
    if (i + 3 < s.n) v3 = s.cnt[i + 3];
    int sv = v0 + v1 + v2 + v3;
    int lane = tid & 31, w = tid >> 5;
    int x = sv;
    #pragma unroll
    for (int o = 1; o < 32; o <<= 1) { int y = __shfl_up_sync(0xffffffffu, x, o); if (lane >= o) x += y; }
    __shared__ int wt[8];
    if (lane == 31) wt[w] = x;
    __syncthreads();
    int add = base;
    for (int j = 0; j < w; j++) add += wt[j];
    int e0 = add + x - sv;
    int e1 = e0 + v0, e2 = e1 + v1, e3 = e2 + v2;
    if (i     < s.n) { s.off[i]     = e0; s.cur[i]     = e0; }
    if (i + 1 < s.n) { s.off[i + 1] = e1; s.cur[i + 1] = e1; }
    if (i + 2 < s.n) { s.off[i + 2] = e2; s.cur[i + 2] = e2; }
    if (i + 3 < s.n) { s.off[i + 3] = e3; s.cur[i + 3] = e3; }
}

__global__ void fill2_kernel(const int* __restrict__ up_src, const int* __restrict__ up_dst,
                             const int* __restrict__ uu_src, const int* __restrict__ uu_dst,
                             int* curP, int* adjP, int* curU, int* adjU) {
    int i = blockIdx.x * blockDim.x + threadIdx.x;
    if (i < EUP) {
        adjP[atomicAdd(&curP[up_src[i]], 1)] = up_dst[i];
    } else {
        int e = i - EUP;
        if (e < EUU) adjU[atomicAdd(&curU[uu_src[e]], 1)] = uu_dst[e];
    }
}

// ---------------- prep: fold all weights (single kernel, 73 blocks) ----------------
__global__ void prep_kernel(const float* __restrict__ Wctx, const float* __restrict__ Wc1,
                            const float* __restrict__ Wu, const float* __restrict__ bu,
                            const float* __restrict__ Wp, const float* __restrict__ bp,
                            const float* __restrict__ Wrf, const float* __restrict__ brf,
                            const float* __restrict__ Wl_pc, const float* __restrict__ Wr_pc,
                            const float* __restrict__ bl_pc,
                            const float* __restrict__ Wl_url, const float* __restrict__ Wr_url,
                            const float* __restrict__ bl_url,
                            const float* __restrict__ bctx, const float* __restrict__ bc1,
                            float* __restrict__ Wf, float* __restrict__ W2pc, float* __restrict__ W2url,
                            float* __restrict__ A1pc, float* __restrict__ A2pc,
                            float* __restrict__ A1url, float* __restrict__ A2url,
                            float* __restrict__ B1pc, float* __restrict__ c1pc,
                            float* __restrict__ B1url, float* __restrict__ c1url,
                            float* __restrict__ AU, float* __restrict__ cU)
{
    int b = blockIdx.x;
    int tid = threadIdx.x;                       // 256
    if (b < 64) {
        __shared__ float sWc1[HD * 64];
        for (int i = tid; i < HD * 64; i += 256) sWc1[i] = Wc1[i];
        __syncthreads();
        int seg = 1 + (b >> 5);
        int r = (b & 31) * 4 + (tid >> 6);
        int c = tid & 63;
        int j = seg * HD + r;
        float acc = 0.f;
        #pragma unroll 8
        for (int m = 0; m < HD; m++) acc = fmaf(Wctx[j * HD + m], sWc1[m * 64 + c], acc);
        Wf[((seg - 1) * HD + r) * 64 + c] = acc;
        return;
    }
    if (b == 64 || b == 65) {
        const float* Wr1 = (b == 64) ? (Wr_pc + HD * HD) : (Wr_url + HD * HD);
        float* W2 = (b == 64) ? W2pc : W2url;
        for (int i = tid; i < HD * HD; i += 256) {
            float v = Wr1[i];
            if ((i >> 7) == (i & 127)) v += 1.f;
            W2[i] = v;
        }
        return;
    }
    if (b >= 66 && b <= 69) {
        const float* Wl;
        float* A;
        if (b == 66)      { Wl = Wl_pc;            A = A1pc; }
        else if (b == 67) { Wl = Wl_pc + HD * HD;  A = A2pc; }
        else if (b == 68) { Wl = Wl_url;           A = A1url; }
        else              { Wl = Wl_url + HD * HD; A = A2url; }
        #pragma unroll
        for (int q = 0; q < 4; q++) {
            int idx = q * 256 + tid;
            int r = idx >> 7, c = idx & 127;
            float acc = 0.f;
            if (r < 6) {
                #pragma unroll 8
                for (int m = 0; m < HD; m++) acc = fmaf(Wu[r * HD + m], Wl[m * HD + c], acc);
            } else if (r == 6) {
                #pragma unroll 8
                for (int m = 0; m < HD; m++) acc = fmaf(bu[m], Wl[m * HD + c], acc);
            }
            A[idx] = acc;
        }
        return;
    }
    if (b == 70 || b == 71) {
        const float* Wsrc = (b == 70) ? Wp : Wrf;
        const float* bsrc = (b == 70) ? bp : brf;
        const float* Wr0  = (b == 70) ? Wr_pc : Wr_url;
        const float* bl0  = (b == 70) ? bl_pc : bl_url;
        float* B1 = (b == 70) ? B1pc : B1url;
        float* c1 = (b == 70) ? c1pc : c1url;
        int Kin = (b == 70) ? 4 : 3;
        int nB = Kin * HD;
        for (int idx = tid; idx < 4 * HD + HD; idx += 256) {
            if (idx < nB) {
                int r = idx / HD, c = idx % HD;
                float acc = 0.f;
                #pragma unroll 8
                for (int m = 0; m < HD; m++) acc = fmaf(Wsrc[r * HD + m], Wr0[m * HD + c], acc);
                B1[idx] = acc;
            } else if (idx < 4 * HD) {
                B1[idx] = 0.f;                        // pad row(s) zero
            } else {
                int c = idx - 4 * HD;
                float acc = bl0[c];
                #pragma unroll 8
                for (int m = 0; m < HD; m++) acc = fmaf(bsrc[m], Wr0[m * HD + c], acc);
                c1[c] = acc;
            }
        }
        return;
    }
    // b == 72: AU = (Wu @ Wctx_U) @ Wc1 ; cU = (bu@Wctx_U + bctx)@Wc1 + bc1
    {
        __shared__ float tmp[7 * HD];
        for (int idx = tid; idx < 7 * HD; idx += 256) {
            int j = idx >> 7, m = idx & 127;
            float acc = 0.f;
            if (j < 6) {
                #pragma unroll 8
                for (int r = 0; r < HD; r++) acc = fmaf(Wu[j * HD + r], Wctx[r * HD + m], acc);
            } else {
                acc = bctx[m];
                #pragma unroll 8
                for (int r = 0; r < HD; r++) acc = fmaf(bu[r], Wctx[r * HD + m], acc);
            }
            tmp[idx] = acc;
        }
        __syncthreads();
        for (int idx = tid; idx < 7 * 64; idx += 256) {
            int j = idx / 64, c = idx % 64;
            float acc = (j == 6) ? bc1[c] : 0.f;
            #pragma unroll 8
            for (int m = 0; m < HD; m++) acc = fmaf(tmp[j * HD + m], Wc1[m * 64 + c], acc);
            if (j < 6) AU[j * 64 + c] = acc;
            else       cU[c] = acc;
        }
    }
}

// ---------------- fused SAGE chain: 64-row tiles (R12 shape), 3 CTAs/SM ----------------
__global__ void __launch_bounds__(256, 3) sage_fused(
    const float* __restrict__ xf, int Kin, const float* __restrict__ mx,
    const float* __restrict__ A1, const float* __restrict__ B1, const float* __restrict__ c1,
    const float* __restrict__ A2, const float* __restrict__ W2, const float* __restrict__ c2,
    const float* __restrict__ Wf64, float* __restrict__ outH, int N)
{
    extern __shared__ float smem[];
    float* T   = smem;                      // [64][ASTRIDE]
    float* sA1 = T + 64 * ASTRIDE;          // 1024
    float* sA2 = sA1 + 8 * HD;              // 1024
    float* sB1 = sA2 + 8 * HD;              // 512 (4 rows, padded)
    float* sc1 = sB1 + 4 * HD;              // 128
    float* sc2 = sc1 + HD;                  // 128
    float* smx = sc2 + HD;                  // 64*8
    float* sxf = smx + 64 * 8;              // 64*4

    const int tid = threadIdx.x;
    const int cq = tid & 15;
    const int rg = tid >> 4;
    const int row0 = blockIdx.x * 64;

    // ---- stage (vectorized; disjoint regions) ----
    ((float4*)sA1)[tid] = ((const float4*)A1)[tid];        // 1024 floats
    ((float4*)sA2)[tid] = ((const float4*)A2)[tid];
    if (tid < 128) {
        ((float4*)sB1)[tid] = ((const float4*)B1)[tid];    // 512 floats (padded rows)
        sc1[tid] = c1[tid];
        sc2[tid] = c2[tid];
    }
    if (tid < 64) {                                        // one mx row each, normalized
        int gr = row0 + tid;
        float4 m0 = make_float4(0.f, 0.f, 0.f, 0.f);
        float4 m1 = make_float4(0.f, 0.f, 0.f, 0.f);
        if (gr < N) {
            m0 = ((const float4*)mx)[gr * 2];
            m1 = ((const float4*)mx)[gr * 2 + 1];
        }
        float cnt = m1.z;
        float inv = (cnt > 0.f) ? (1.f / cnt) : 0.f;
        m0.x *= inv; m0.y *= inv; m0.z *= inv; m0.w *= inv;
        m1.x *= inv; m1.y *= inv;
        m1.z = (cnt > 0.f) ? 1.f : 0.f;
        m1.w = 0.f;
        ((float4*)smx)[tid * 2]     = m0;
        ((float4*)smx)[tid * 2 + 1] = m1;
    }
    {                                                      // sxf: 64 rows x 4 (padded) = 256 entries
        int r = tid >> 2, j = tid & 3;
        int gr = row0 + r;
        sxf[tid] = (gr < N && j < Kin) ? xf[gr * Kin + j] : 0.f;
    }
    __syncthreads();

    // ---- step1: T = relu(mx@A1 + xf@B1(4 padded rows) + c1) ----
    #pragma unroll
    for (int i = 0; i < 4; i++) {
        int r = rg + i * 16;
        float m[8];
        #pragma unroll
        for (int j = 0; j < 8; j++) m[j] = smx[r * 8 + j];
        float xr[4];
        #pragma unroll
        for (int j = 0; j < 4; j++) xr[j] = sxf[r * 4 + j];
        float o[8];
        #pragma unroll
        for (int jj = 0; jj < 8; jj++) {
            int c = cq * 8 + jj;
            float v = sc1[c];
            #pragma unroll
            for (int j = 0; j < 8; j++) v = fmaf(m[j], sA1[j * HD + c], v);
            #pragma unroll
            for (int j = 0; j < 4; j++) v = fmaf(xr[j], sB1[j * HD + c], v);
            o[jj] = fmaxf(v, 0.f);
        }
        float* tr = &T[r * ASTRIDE + cq * 8];
        #pragma unroll
        for (int p = 0; p < 4; p++) *(float2*)(tr + p * 2) = make_float2(o[2*p], o[2*p+1]);
    }
    __syncthreads();

    // ---- step2: acc = T@W2 (regs), then T <- relu(acc + mx@A2 + c2) ----
    {
        const ulonglong2* W2v = (const ulonglong2*)W2;
        u64 acc[4][4];
        #pragma unroll
        for (int i = 0; i < 4; i++)
            #pragma unroll
            for (int p = 0; p < 4; p++) acc[i][p] = 0ULL;
        #pragma unroll 2
        for (int k = 0; k < 128; k += 2) {
            ulonglong2 w10a = W2v[k * 32 + cq * 2];
            ulonglong2 w10b = W2v[k * 32 + cq * 2 + 1];
            ulonglong2 w11a = W2v[(k + 1) * 32 + cq * 2];
            ulonglong2 w11b = W2v[(k + 1) * 32 + cq * 2 + 1];
            #pragma unroll
            for (int i = 0; i < 4; i++) {
                float2 a2 = *(const float2*)&T[(rg + i * 16) * ASTRIDE + k];
                u64 aa0 = f2pack(a2.x), aa1 = f2pack(a2.y);
                acc[i][0] = f2fma(aa0, w10a.x, acc[i][0]);
                acc[i][1] = f2fma(aa0, w10a.y, acc[i][1]);
                acc[i][2] = f2fma(aa0, w10b.x, acc[i][2]);
                acc[i][3] = f2fma(aa0, w10b.y, acc[i][3]);
                acc[i][0] = f2fma(aa1, w11a.x, acc[i][0]);
                acc[i][1] = f2fma(aa1, w11a.y, acc[i][1]);
                acc[i][2] = f2fma(aa1, w11b.x, acc[i][2]);
                acc[i][3] = f2fma(aa1, w11b.y, acc[i][3]);
            }
        }
        __syncthreads();   // all T reads complete before overwrite
        #pragma unroll
        for (int i = 0; i < 4; i++) {
            int r = rg + i * 16;
            float o[8];
            f2unpack(acc[i][0], o[0], o[1]);
            f2unpack(acc[i][1], o[2], o[3]);
            f2unpack(acc[i][2], o[4], o[5]);
            f2unpack(acc[i][3], o[6], o[7]);
            float m[8];
            #pragma unroll
            for (int j = 0; j < 8; j++) m[j] = smx[r * 8 + j];
            #pragma unroll
            for (int jj = 0; jj < 8; jj++) {
                int c = cq * 8 + jj;
                float v = o[jj] + sc2[c];
                #pragma unroll
                for (int j = 0; j < 8; j++) v = fmaf(m[j], sA2[j * HD + c], v);
                o[jj] = fmaxf(v, 0.f);
            }
            float* tr = &T[r * ASTRIDE + cq * 8];
            #pragma unroll
            for (int p = 0; p < 4; p++) *(float2*)(tr + p * 2) = make_float2(o[2*p], o[2*p+1]);
        }
    }
    __syncthreads();

    // ---- step3: outH = T @ Wf64 ----
    {
        const ulonglong2* Wv = (const ulonglong2*)Wf64;
        u64 acc[4][2];
        #pragma unroll
        for (int i = 0; i < 4; i++) { acc[i][0] = 0ULL; acc[i][1] = 0ULL; }
        #pragma unroll 2
        for (int k = 0; k < 128; k += 2) {
            ulonglong2 wA = Wv[k * 16 + cq];
            ulonglong2 wB = Wv[(k + 1) * 16 + cq];
            #pragma unroll
            for (int i = 0; i < 4; i++) {
                float2 a2 = *(const float2*)&T[(rg + i * 16) * ASTRIDE + k];
                u64 aa0 = f2pack(a2.x), aa1 = f2pack(a2.y);
                acc[i][0] = f2fma(aa0, wA.x, acc[i][0]);
                acc[i][1] = f2fma(aa0, wA.y, acc[i][1]);
                acc[i][0] = f2fma(aa1, wB.x, acc[i][0]);
                acc[i][1] = f2fma(aa1, wB.y, acc[i][1]);
            }
        }
        const int c0 = cq * 4;
        #pragma unroll
        for (int i = 0; i < 4; i++) {
            int gr = row0 + rg + i * 16;
            if (gr >= N) continue;
            float o[4];
            f2unpack(acc[i][0], o[0], o[1]);
            f2unpack(acc[i][1], o[2], o[3]);
            *(float4*)(outH + gr * 64 + c0) = make_float4(o[0], o[1], o[2], o[3]);
        }
    }
}

// ---------------- fused gather + user-term + classifier: 1 warp/user ----------------
__global__ void __launch_bounds__(256) gather_cls_kernel(
    const float* __restrict__ xu, const float* __restrict__ AU, const float* __restrict__ cU,
    const float* __restrict__ pcH, const float* __restrict__ urlH,
    const int* __restrict__ offP, const int* __restrict__ adjP,
    const int* __restrict__ offR, const int* __restrict__ adjR,
    const float* __restrict__ Wc2, const float* __restrict__ bc2,
    float* __restrict__ out, int N)
{
    __shared__ float sAU[6 * 64];
    __shared__ float scU[64];
    __shared__ float sW2[128];
    int tid = threadIdx.x;                    // 256 = 8 warps = 8 users
    for (int i = tid; i < 384; i += 256) sAU[i] = AU[i];
    if (tid < 64) scU[tid] = cU[tid];
    if (tid >= 64 && tid < 192) sW2[tid - 64] = Wc2[tid - 64];
    __syncthreads();

    int w = tid >> 5, lane = tid & 31;
    int u = blockIdx.x * 8 + w;
    if (u >= N) return;
    int c0 = lane * 2;

    float a0 = scU[c0], a1 = scU[c0 + 1];
    #pragma unroll
    for (int j = 0; j < 6; j++) {
        float xv = __ldg(&xu[u * 6 + j]);
        a0 = fmaf(xv, sAU[j * 64 + c0], a0);
        a1 = fmaf(xv, sAU[j * 64 + c0 + 1], a1);
    }
    {
        int e = offP[u], end = offP[u + 1];
        for (; e + 2 <= end; e += 2) {
            int i0 = adjP[e], i1 = adjP[e + 1];
            float2 v0 = *(const float2*)&pcH[i0 * 64 + c0];
            float2 v1 = *(const float2*)&pcH[i1 * 64 + c0];
            a0 += v0.x + v1.x;
            a1 += v0.y + v1.y;
        }
        if (e < end) {
            float2 v = *(const float2*)&pcH[adjP[e] * 64 + c0];
            a0 += v.x; a1 += v.y;
        }
    }
    {
        int e = offR[u], end = offR[u + 1];
        for (; e + 4 <= end; e += 4) {
            int i0 = adjR[e], i1 = adjR[e + 1], i2 = adjR[e + 2], i3 = adjR[e + 3];
            float2 v0 = *(const float2*)&urlH[i0 * 64 + c0];
            float2 v1 = *(const float2*)&urlH[i1 * 64 + c0];
            float2 v2 = *(const float2*)&urlH[i2 * 64 + c0];
            float2 v3 = *(const float2*)&urlH[i3 * 64 + c0];
            a0 += (v0.x + v1.x) + (v2.x + v3.x);
            a1 += (v0.y + v1.y) + (v2.y + v3.y);
        }
        for (; e < end; e++) {
            float2 v = *(const float2*)&urlH[adjR[e] * 64 + c0];
            a0 += v.x; a1 += v.y;
        }
    }
    float h0 = fmaxf(a0, 0.f), h1 = fmaxf(a1, 0.f);
    float p0 = fmaf(h0, sW2[c0 * 2],     h1 * sW2[(c0 + 1) * 2]);
    float p1 = fmaf(h0, sW2[c0 * 2 + 1], h1 * sW2[(c0 + 1) * 2 + 1]);
    #pragma unroll
    for (int o = 16; o > 0; o >>= 1) {
        p0 += __shfl_down_sync(0xffffffffu, p0, o);
        p1 += __shfl_down_sync(0xffffffffu, p1, o);
    }
    if (lane == 0) {
        out[u * 2 + 0] = p0 + bc2[0];
        out[u * 2 + 1] = p1 + bc2[1];
    }
}

// ---------------- streams/events (static init) ----------------
struct StreamCtx {
    cudaStream_t s1, s2, s3;
    cudaEvent_t evRoot, evPrep, evPC, evURL;
    StreamCtx() {
        cudaStreamCreateWithFlags(&s1, cudaStreamNonBlocking);
        cudaStreamCreateWithFlags(&s2, cudaStreamNonBlocking);
        cudaStreamCreateWithFlags(&s3, cudaStreamNonBlocking);
        cudaEventCreateWithFlags(&evRoot, cudaEventDisableTiming);
        cudaEventCreateWithFlags(&evPrep, cudaEventDisableTiming);
        cudaEventCreateWithFlags(&evPC,   cudaEventDisableTiming);
        cudaEventCreateWithFlags(&evURL,  cudaEventDisableTiming);
    }
};
static StreamCtx g_sc;

// ---------------- host orchestration ----------------
#define SYMADDR(p, s) do { void* _t; cudaGetSymbolAddress(&_t, s); p = (decltype(p))_t; } while (0)

extern "C" void kernel_launch(void* const* d_in, const int* in_sizes, int n_in,
                              void* d_out, int out_size) {
    const float* x_user = (const float*)d_in[0];
    const float* x_pc   = (const float*)d_in[1];
    const float* x_url  = (const float*)d_in[2];
    const int* up_src   = (const int*)d_in[3];
    const int* up_dst   = (const int*)d_in[4];
    const int* uu_src   = (const int*)d_in[5];
    const int* uu_dst   = (const int*)d_in[6];
    const float* Wu = (const float*)d_in[7];
    const float* bu = (const float*)d_in[8];
    const float* Wp = (const float*)d_in[9];
    const float* bp = (const float*)d_in[10];
    const float* Wrf = (const float*)d_in[11];
    const float* brf = (const float*)d_in[12];
    const float* Wl_pc = (const float*)d_in[13];
    const float* bl_pc = (const float*)d_in[14];
    const float* Wr_pc = (const float*)d_in[15];
    const float* Wl_url = (const float*)d_in[16];
    const float* bl_url = (const float*)d_in[17];
    const float* Wr_url = (const float*)d_in[18];
    const float* Wctx = (const float*)d_in[19];
    const float* bctx = (const float*)d_in[20];
    const float* Wc1 = (const float*)d_in[21];
    const float* bc1 = (const float*)d_in[22];
    const float* Wc2 = (const float*)d_in[23];
    const float* bc2 = (const float*)d_in[24];
    float* out = (float*)d_out;

    float *mx_pc, *mx_url, *pcH, *urlH;
    float *Wf, *W2pc, *W2url, *A1pc, *A2pc, *A1url, *A2url, *B1pc, *c1pc, *B1url, *c1url, *AU, *cU;
    SYMADDR(mx_pc, g_mx_pc); SYMADDR(mx_url, g_mx_url);
    SYMADDR(pcH, g_pcH); SYMADDR(urlH, g_urlH);
    SYMADDR(Wf, g_Wf); SYMADDR(W2pc, g_W2pc); SYMADDR(W2url, g_W2url);
    SYMADDR(A1pc, g_A1pc); SYMADDR(A2pc, g_A2pc); SYMADDR(A1url, g_A1url); SYMADDR(A2url, g_A2url);
    SYMADDR(B1pc, g_B1pc); SYMADDR(c1pc, g_c1pc); SYMADDR(B1url, g_B1url); SYMADDR(c1url, g_c1url);
    SYMADDR(AU, g_AU); SYMADDR(cU, g_cU);

    int *cnt_ups, *off_ups, *cur_ups, *adj_ups;
    int *cnt_uus, *off_uus, *cur_uus, *adj_uus;
    SYMADDR(cnt_ups, g_cnt_ups); SYMADDR(off_ups, g_off_ups); SYMADDR(cur_ups, g_cur_ups); SYMADDR(adj_ups, g_adj_ups);
    SYMADDR(cnt_uus, g_cnt_uus); SYMADDR(off_uus, g_off_uus); SYMADDR(cur_uus, g_cur_uus); SYMADDR(adj_uus, g_adj_uus);

    const int SAGE_SMEM = (64 * ASTRIDE + 8 * HD * 2 + 4 * HD + 2 * HD + 64 * 8 + 64 * 4) * 4;  // 48128 B
    cudaFuncSetAttribute(sage_fused, cudaFuncAttributeMaxDynamicSharedMemorySize, SAGE_SMEM);

    cudaStream_t s0 = 0;
    cudaStream_t s1 = g_sc.s1, s2 = g_sc.s2, s3 = g_sc.s3;

    // ---- fork ----
    cudaEventRecord(g_sc.evRoot, s0);
    cudaStreamWaitEvent(s1, g_sc.evRoot, 0);
    cudaStreamWaitEvent(s2, g_sc.evRoot, 0);
    cudaStreamWaitEvent(s3, g_sc.evRoot, 0);

    // ---- s3: weight folding ----
    prep_kernel<<<73, 256, 0, s3>>>(Wctx, Wc1, Wu, bu, Wp, bp, Wrf, brf,
                                    Wl_pc, Wr_pc, bl_pc, Wl_url, Wr_url, bl_url,
                                    bctx, bc1,
                                    Wf, W2pc, W2url, A1pc, A2pc, A1url, A2url,
                                    B1pc, c1pc, B1url, c1url, AU, cU);
    cudaEventRecord(g_sc.evPrep, s3);

    // ---- s2: url chain (own accum -> own sage) ----
    cudaMemsetAsync(mx_url, 0, NURL * 8 * sizeof(float), s2);
    accum_kernel<<<(EUU + 255) / 256, 256, 0, s2>>>(x_user, uu_src, uu_dst, EUU, mx_url);
    cudaStreamWaitEvent(s2, g_sc.evPrep, 0);
    sage_fused<<<(NURL + 63) / 64, 256, SAGE_SMEM, s2>>>(x_url, 3, mx_url,
                                                         A1url, B1url, c1url,
                                                         A2url, W2url, bl_url + HD,
                                                         Wf + HD * 64, urlH, NURL);
    cudaEventRecord(g_sc.evURL, s2);

    // ---- s1: pc chain (own accum -> own sage; starts without waiting for url accum) ----
    cudaMemsetAsync(mx_pc, 0, NPC * 8 * sizeof(float), s1);
    accum_kernel<<<(EUP + 255) / 256, 256, 0, s1>>>(x_user, up_src, up_dst, EUP, mx_pc);
    cudaStreamWaitEvent(s1, g_sc.evPrep, 0);
    sage_fused<<<(NPC + 63) / 64, 256, SAGE_SMEM, s1>>>(x_pc, 4, mx_pc,
                                                        A1pc, B1pc, c1pc,
                                                        A2pc, W2pc, bl_pc + HD,
                                                        Wf, pcH, NPC);
    cudaEventRecord(g_sc.evPC, s1);

    // ---- s0: src-side CSR (overlapped) ----
    cudaMemsetAsync(cnt_ups, 0, NU * sizeof(int), s0);
    cudaMemsetAsync(cnt_uus, 0, NU * sizeof(int), s0);
    count2_kernel<<<(EUP + EUU + 255) / 256, 256, 0, s0>>>(up_src, uu_src, cnt_ups, cnt_uus);
    SetDesc d2{cnt_ups, off_ups, cur_ups, NU};
    SetDesc d3{cnt_uus, off_uus, cur_uus, NU};
    dim3 gScan((NU + 1023) / 1024, 2);
    scanA_kernel<<<gScan, 256, 0, s0>>>(d2, d3);
    scanB_kernel<<<2, 128, 0, s0>>>(d2, d3);
    scanC_kernel<<<gScan, 256, 0, s0>>>(d2, d3);
    fill2_kernel<<<(EUP + EUU + 255) / 256, 256, 0, s0>>>(up_src, up_dst, uu_src, uu_dst,
                                                          cur_ups, adj_ups, cur_uus, adj_uus);

    // ---- join on s0: fused gather + classifier ----
    cudaStreamWaitEvent(s0, g_sc.evPC, 0);
    cudaStreamWaitEvent(s0, g_sc.evURL, 0);
    gather_cls_kernel<<<(NU + 7) / 8, 256, 0, s0>>>(x_user, AU, cU, pcH, urlH,
                                                    off_ups, adj_ups, off_uus, adj_uus,
                                                    Wc2, bc2, out, NU);
}

// round 15
// speedup vs baseline: 1.1013x; 1.0633x over previous
#include <cuda_runtime.h>
#include <cstdint>

#define NU   100000
#define NPC  20000
#define NURL 50000
#define EUP  250000
#define EUU  500000
#define HD   128
#define MAXB 128
#define ASTRIDE 132

// ---------------- scratch ----------------
__device__ __align__(16) float g_mx_pc[NPC*8];    // cols 0..5 sum, 6 count, 7 zero
__device__ __align__(16) float g_mx_url[NURL*8];
__device__ __align__(16) float g_pcH[NPC*64];
__device__ __align__(16) float g_urlH[NURL*64];

// folded weights
__device__ __align__(16) float g_Wf[2*HD*64];     // WfP | WfR
__device__ __align__(16) float g_W2pc[HD*HD];
__device__ __align__(16) float g_W2url[HD*HD];
__device__ __align__(16) float g_A1pc[8*HD];
__device__ __align__(16) float g_A2pc[8*HD];
__device__ __align__(16) float g_A1url[8*HD];
__device__ __align__(16) float g_A2url[8*HD];
__device__ __align__(16) float g_B1pc[4*HD];
__device__ __align__(16) float g_c1pc[HD];
__device__ __align__(16) float g_B1url[4*HD];     // padded to 4 rows (row 3 zero for url)
__device__ __align__(16) float g_c1url[HD];
__device__ __align__(16) float g_AU[6*64];
__device__ __align__(16) float g_cU[64];

// src-side CSR (for gather_cls)
__device__ __align__(16) int g_cnt_ups[NU];  __device__ int g_off_ups[NU+1];  __device__ int g_cur_ups[NU];  __device__ int g_adj_ups[EUP];
__device__ __align__(16) int g_cnt_uus[NU];  __device__ int g_off_uus[NU+1];  __device__ int g_cur_uus[NU];  __device__ int g_adj_uus[EUU];
__device__ int g_part[2*MAXB];

// ---------------- f32x2 helpers ----------------
typedef unsigned long long u64;
__device__ __forceinline__ u64 f2fma(u64 a, u64 b, u64 c) {
    u64 d; asm("fma.rn.f32x2 %0, %1, %2, %3;" : "=l"(d) : "l"(a), "l"(b), "l"(c)); return d;
}
__device__ __forceinline__ u64 f2pack(float x) {
    u64 r; asm("mov.b64 %0, {%1, %1};" : "=l"(r) : "f"(x)); return r;
}
__device__ __forceinline__ void f2unpack(u64 v, float& x, float& y) {
    asm("mov.b64 {%0, %1}, %2;" : "=f"(x), "=f"(y) : "l"(v));
}
__device__ __forceinline__ void red_v4(float* p, float a, float b, float c, float d) {
    asm volatile("red.global.add.v4.f32 [%0], {%1, %2, %3, %4};"
                 :: "l"(p), "f"(a), "f"(b), "f"(c), "f"(d) : "memory");
}

// ---------------- per-type edge-parallel mx accumulation ----------------
__global__ void accum_kernel(const float* __restrict__ xu,
                             const int* __restrict__ src, const int* __restrict__ dst,
                             int E, float* __restrict__ mx) {
    int i = blockIdx.x * blockDim.x + threadIdx.x;
    if (i >= E) return;
    int s = src[i], d = dst[i];
    const float2* xr = (const float2*)(xu + s * 6);
    float2 a = xr[0], b = xr[1], c = xr[2];
    float* m = mx + d * 8;
    red_v4(m,     a.x, a.y, b.x, b.y);
    red_v4(m + 4, c.x, c.y, 1.f, 0.f);
}

// ---------------- src-side CSR ----------------
__global__ void count2_kernel(const int* __restrict__ up_src, const int* __restrict__ uu_src,
                              int* cntP, int* cntU) {
    int i = blockIdx.x * blockDim.x + threadIdx.x;
    if (i < EUP) atomicAdd(&cntP[up_src[i]], 1);
    else {
        int e = i - EUP;
        if (e < EUU) atomicAdd(&cntU[uu_src[e]], 1);
    }
}

struct SetDesc { const int* cnt; int* off; int* cur; int n; };

__global__ void scanA_kernel(SetDesc s0, SetDesc s1) {
    SetDesc s = (blockIdx.y == 0) ? s0 : s1;
    int nb = (s.n + 1023) >> 10;
    if ((int)blockIdx.x >= nb) return;
    int tid = threadIdx.x;
    int i = blockIdx.x * 1024 + tid * 4;
    int sum = 0;
    #pragma unroll
    for (int j = 0; j < 4; j++) { int idx = i + j; if (idx < s.n) sum += s.cnt[idx]; }
    #pragma unroll
    for (int o = 16; o > 0; o >>= 1) sum += __shfl_down_sync(0xffffffffu, sum, o);
    __shared__ int ws[8];
    if ((tid & 31) == 0) ws[tid >> 5] = sum;
    __syncthreads();
    if (tid < 8) {
        int v = ws[tid];
        #pragma unroll
        for (int o = 4; o > 0; o >>= 1) v += __shfl_down_sync(0xffu, v, o);
        if (tid == 0) g_part[blockIdx.y * MAXB + blockIdx.x] = v;
    }
}

__global__ void scanB_kernel(SetDesc s0, SetDesc s1) {
    SetDesc s = (blockIdx.x == 0) ? s0 : s1;
    int nb = (s.n + 1023) >> 10;
    int tid = threadIdx.x;
    int v = (tid < nb) ? g_part[blockIdx.x * MAXB + tid] : 0;
    int lane = tid & 31, w = tid >> 5;
    int x = v;
    #pragma unroll
    for (int o = 1; o < 32; o <<= 1) { int y = __shfl_up_sync(0xffffffffu, x, o); if (lane >= o) x += y; }
    __shared__ int wt[4];
    if (lane == 31) wt[w] = x;
    __syncthreads();
    int add = 0;
    for (int j = 0; j < w; j++) add += wt[j];
    int incl = x + add;
    if (tid < nb) g_part[blockIdx.x * MAXB + tid] = incl - v;
    if (tid == 127) s.off[s.n] = incl;
}

__global__ void scanC_kernel(SetDesc s0, SetDesc s1) {
    SetDesc s = (blockIdx.y == 0) ? s0 : s1;
    int nb = (s.n + 1023) >> 10;
    if ((int)blockIdx.x >= nb) return;
    int tid = threadIdx.x;
    int base = g_part[blockIdx.y * MAXB + blockIdx.x];
    int i = blockIdx.x * 1024 + tid * 4;
    int v0 = 0, v1 = 0, v2 = 0, v3 = 0;
    if (i     < s.n) v0 = s.cnt[i];
    if (i + 1 < s.n) v1 = s.cnt[i + 1];
    if (i + 2 < s.n) v2 = s.cnt[i + 2];
    if (i + 3 < s.n) v3 = s.cnt[i + 3];
    int sv = v0 + v1 + v2 + v3;
    int lane = tid & 31, w = tid >> 5;
    int x = sv;
    #pragma unroll
    for (int o = 1; o < 32; o <<= 1) { int y = __shfl_up_sync(0xffffffffu, x, o); if (lane >= o) x += y; }
    __shared__ int wt[8];
    if (lane == 31) wt[w] = x;
    __syncthreads();
    int add = base;
    for (int j = 0; j < w; j++) add += wt[j];
    int e0 = add + x - sv;
    int e1 = e0 + v0, e2 = e1 + v1, e3 = e2 + v2;
    if (i     < s.n) { s.off[i]     = e0; s.cur[i]     = e0; }
    if (i + 1 < s.n) { s.off[i + 1] = e1; s.cur[i + 1] = e1; }
    if (i + 2 < s.n) { s.off[i + 2] = e2; s.cur[i + 2] = e2; }
    if (i + 3 < s.n) { s.off[i + 3] = e3; s.cur[i + 3] = e3; }
}

__global__ void fill2_kernel(const int* __restrict__ up_src, const int* __restrict__ up_dst,
                             const int* __restrict__ uu_src, const int* __restrict__ uu_dst,
                             int* curP, int* adjP, int* curU, int* adjU) {
    int i = blockIdx.x * blockDim.x + threadIdx.x;
    if (i < EUP) {
        adjP[atomicAdd(&curP[up_src[i]], 1)] = up_dst[i];
    } else {
        int e = i - EUP;
        if (e < EUU) adjU[atomicAdd(&curU[uu_src[e]], 1)] = uu_dst[e];
    }
}

// ---------------- prep: fold all weights (single kernel, 73 blocks) ----------------
__global__ void prep_kernel(const float* __restrict__ Wctx, const float* __restrict__ Wc1,
                            const float* __restrict__ Wu, const float* __restrict__ bu,
                            const float* __restrict__ Wp, const float* __restrict__ bp,
                            const float* __restrict__ Wrf, const float* __restrict__ brf,
                            const float* __restrict__ Wl_pc, const float* __restrict__ Wr_pc,
                            const float* __restrict__ bl_pc,
                            const float* __restrict__ Wl_url, const float* __restrict__ Wr_url,
                            const float* __restrict__ bl_url,
                            const float* __restrict__ bctx, const float* __restrict__ bc1,
                            float* __restrict__ Wf, float* __restrict__ W2pc, float* __restrict__ W2url,
                            float* __restrict__ A1pc, float* __restrict__ A2pc,
                            float* __restrict__ A1url, float* __restrict__ A2url,
                            float* __restrict__ B1pc, float* __restrict__ c1pc,
                            float* __restrict__ B1url, float* __restrict__ c1url,
                            float* __restrict__ AU, float* __restrict__ cU)
{
    int b = blockIdx.x;
    int tid = threadIdx.x;                       // 256
    if (b < 64) {
        __shared__ float sWc1[HD * 64];
        for (int i = tid; i < HD * 64; i += 256) sWc1[i] = Wc1[i];
        __syncthreads();
        int seg = 1 + (b >> 5);
        int r = (b & 31) * 4 + (tid >> 6);
        int c = tid & 63;
        int j = seg * HD + r;
        float acc = 0.f;
        #pragma unroll 8
        for (int m = 0; m < HD; m++) acc = fmaf(Wctx[j * HD + m], sWc1[m * 64 + c], acc);
        Wf[((seg - 1) * HD + r) * 64 + c] = acc;
        return;
    }
    if (b == 64 || b == 65) {
        const float* Wr1 = (b == 64) ? (Wr_pc + HD * HD) : (Wr_url + HD * HD);
        float* W2 = (b == 64) ? W2pc : W2url;
        for (int i = tid; i < HD * HD; i += 256) {
            float v = Wr1[i];
            if ((i >> 7) == (i & 127)) v += 1.f;
            W2[i] = v;
        }
        return;
    }
    if (b >= 66 && b <= 69) {
        const float* Wl;
        float* A;
        if (b == 66)      { Wl = Wl_pc;            A = A1pc; }
        else if (b == 67) { Wl = Wl_pc + HD * HD;  A = A2pc; }
        else if (b == 68) { Wl = Wl_url;           A = A1url; }
        else              { Wl = Wl_url + HD * HD; A = A2url; }
        #pragma unroll
        for (int q = 0; q < 4; q++) {
            int idx = q * 256 + tid;
            int r = idx >> 7, c = idx & 127;
            float acc = 0.f;
            if (r < 6) {
                #pragma unroll 8
                for (int m = 0; m < HD; m++) acc = fmaf(Wu[r * HD + m], Wl[m * HD + c], acc);
            } else if (r == 6) {
                #pragma unroll 8
                for (int m = 0; m < HD; m++) acc = fmaf(bu[m], Wl[m * HD + c], acc);
            }
            A[idx] = acc;
        }
        return;
    }
    if (b == 70 || b == 71) {
        const float* Wsrc = (b == 70) ? Wp : Wrf;
        const float* bsrc = (b == 70) ? bp : brf;
        const float* Wr0  = (b == 70) ? Wr_pc : Wr_url;
        const float* bl0  = (b == 70) ? bl_pc : bl_url;
        float* B1 = (b == 70) ? B1pc : B1url;
        float* c1 = (b == 70) ? c1pc : c1url;
        int Kin = (b == 70) ? 4 : 3;
        int nB = Kin * HD;
        for (int idx = tid; idx < 4 * HD + HD; idx += 256) {
            if (idx < nB) {
                int r = idx / HD, c = idx % HD;
                float acc = 0.f;
                #pragma unroll 8
                for (int m = 0; m < HD; m++) acc = fmaf(Wsrc[r * HD + m], Wr0[m * HD + c], acc);
                B1[idx] = acc;
            } else if (idx < 4 * HD) {
                B1[idx] = 0.f;                        // pad row(s) zero
            } else {
                int c = idx - 4 * HD;
                float acc = bl0[c];
                #pragma unroll 8
                for (int m = 0; m < HD; m++) acc = fmaf(bsrc[m], Wr0[m * HD + c], acc);
                c1[c] = acc;
            }
        }
        return;
    }
    // b == 72: AU = (Wu @ Wctx_U) @ Wc1 ; cU = (bu@Wctx_U + bctx)@Wc1 + bc1
    {
        __shared__ float tmp[7 * HD];
        for (int idx = tid; idx < 7 * HD; idx += 256) {
            int j = idx >> 7, m = idx & 127;
            float acc = 0.f;
            if (j < 6) {
                #pragma unroll 8
                for (int r = 0; r < HD; r++) acc = fmaf(Wu[j * HD + r], Wctx[r * HD + m], acc);
            } else {
                acc = bctx[m];
                #pragma unroll 8
                for (int r = 0; r < HD; r++) acc = fmaf(bu[r], Wctx[r * HD + m], acc);
            }
            tmp[idx] = acc;
        }
        __syncthreads();
        for (int idx = tid; idx < 7 * 64; idx += 256) {
            int j = idx / 64, c = idx % 64;
            float acc = (j == 6) ? bc1[c] : 0.f;
            #pragma unroll 8
            for (int m = 0; m < HD; m++) acc = fmaf(tmp[j * HD + m], Wc1[m * 64 + c], acc);
            if (j < 6) AU[j * 64 + c] = acc;
            else       cU[c] = acc;
        }
    }
}

// ---------------- fused SAGE chain: 64-row tiles, 3 CTAs/SM ----------------
__global__ void __launch_bounds__(256, 3) sage_fused(
    const float* __restrict__ xf, int Kin, const float* __restrict__ mx,
    const float* __restrict__ A1, const float* __restrict__ B1, const float* __restrict__ c1,
    const float* __restrict__ A2, const float* __restrict__ W2, const float* __restrict__ c2,
    const float* __restrict__ Wf64, float* __restrict__ outH, int N)
{
    extern __shared__ float smem[];
    float* T   = smem;                      // [64][ASTRIDE]
    float* sA1 = T + 64 * ASTRIDE;          // 1024
    float* sA2 = sA1 + 8 * HD;              // 1024
    float* sB1 = sA2 + 8 * HD;              // 512 (4 rows, padded)
    float* sc1 = sB1 + 4 * HD;              // 128
    float* sc2 = sc1 + HD;                  // 128
    float* smx = sc2 + HD;                  // 64*8
    float* sxf = smx + 64 * 8;              // 64*4

    const int tid = threadIdx.x;
    const int cq = tid & 15;
    const int rg = tid >> 4;
    const int row0 = blockIdx.x * 64;

    // ---- stage (vectorized; disjoint regions) ----
    ((float4*)sA1)[tid] = ((const float4*)A1)[tid];        // 1024 floats
    ((float4*)sA2)[tid] = ((const float4*)A2)[tid];
    if (tid < 128) {
        ((float4*)sB1)[tid] = ((const float4*)B1)[tid];    // 512 floats (padded rows)
        sc1[tid] = c1[tid];
        sc2[tid] = c2[tid];
    }
    if (tid < 64) {                                        // one mx row each, normalized
        int gr = row0 + tid;
        float4 m0 = make_float4(0.f, 0.f, 0.f, 0.f);
        float4 m1 = make_float4(0.f, 0.f, 0.f, 0.f);
        if (gr < N) {
            m0 = ((const float4*)mx)[gr * 2];
            m1 = ((const float4*)mx)[gr * 2 + 1];
        }
        float cnt = m1.z;
        float inv = (cnt > 0.f) ? (1.f / cnt) : 0.f;
        m0.x *= inv; m0.y *= inv; m0.z *= inv; m0.w *= inv;
        m1.x *= inv; m1.y *= inv;
        m1.z = (cnt > 0.f) ? 1.f : 0.f;
        m1.w = 0.f;
        ((float4*)smx)[tid * 2]     = m0;
        ((float4*)smx)[tid * 2 + 1] = m1;
    }
    {                                                      // sxf: 64 rows x 4 (padded) = 256 entries
        int r = tid >> 2, j = tid & 3;
        int gr = row0 + r;
        sxf[tid] = (gr < N && j < Kin) ? xf[gr * Kin + j] : 0.f;
    }
    __syncthreads();

    // ---- step1: T = relu(mx@A1 + xf@B1(4 padded rows) + c1) ----
    #pragma unroll
    for (int i = 0; i < 4; i++) {
        int r = rg + i * 16;
        float m[8];
        #pragma unroll
        for (int j = 0; j < 8; j++) m[j] = smx[r * 8 + j];
        float xr[4];
        #pragma unroll
        for (int j = 0; j < 4; j++) xr[j] = sxf[r * 4 + j];
        float o[8];
        #pragma unroll
        for (int jj = 0; jj < 8; jj++) {
            int c = cq * 8 + jj;
            float v = sc1[c];
            #pragma unroll
            for (int j = 0; j < 8; j++) v = fmaf(m[j], sA1[j * HD + c], v);
            #pragma unroll
            for (int j = 0; j < 4; j++) v = fmaf(xr[j], sB1[j * HD + c], v);
            o[jj] = fmaxf(v, 0.f);
        }
        float* tr = &T[r * ASTRIDE + cq * 8];
        #pragma unroll
        for (int p = 0; p < 4; p++) *(float2*)(tr + p * 2) = make_float2(o[2*p], o[2*p+1]);
    }
    __syncthreads();

    // ---- step2: acc = T@W2 (regs), then T <- relu(acc + mx@A2 + c2) ----
    {
        const ulonglong2* W2v = (const ulonglong2*)W2;
        u64 acc[4][4];
        #pragma unroll
        for (int i = 0; i < 4; i++)
            #pragma unroll
            for (int p = 0; p < 4; p++) acc[i][p] = 0ULL;
        #pragma unroll 2
        for (int k = 0; k < 128; k += 2) {
            ulonglong2 w10a = W2v[k * 32 + cq * 2];
            ulonglong2 w10b = W2v[k * 32 + cq * 2 + 1];
            ulonglong2 w11a = W2v[(k + 1) * 32 + cq * 2];
            ulonglong2 w11b = W2v[(k + 1) * 32 + cq * 2 + 1];
            #pragma unroll
            for (int i = 0; i < 4; i++) {
                float2 a2 = *(const float2*)&T[(rg + i * 16) * ASTRIDE + k];
                u64 aa0 = f2pack(a2.x), aa1 = f2pack(a2.y);
                acc[i][0] = f2fma(aa0, w10a.x, acc[i][0]);
                acc[i][1] = f2fma(aa0, w10a.y, acc[i][1]);
                acc[i][2] = f2fma(aa0, w10b.x, acc[i][2]);
                acc[i][3] = f2fma(aa0, w10b.y, acc[i][3]);
                acc[i][0] = f2fma(aa1, w11a.x, acc[i][0]);
                acc[i][1] = f2fma(aa1, w11a.y, acc[i][1]);
                acc[i][2] = f2fma(aa1, w11b.x, acc[i][2]);
                acc[i][3] = f2fma(aa1, w11b.y, acc[i][3]);
            }
        }
        __syncthreads();   // all T reads complete before overwrite
        #pragma unroll
        for (int i = 0; i < 4; i++) {
            int r = rg + i * 16;
            float o[8];
            f2unpack(acc[i][0], o[0], o[1]);
            f2unpack(acc[i][1], o[2], o[3]);
            f2unpack(acc[i][2], o[4], o[5]);
            f2unpack(acc[i][3], o[6], o[7]);
            float m[8];
            #pragma unroll
            for (int j = 0; j < 8; j++) m[j] = smx[r * 8 + j];
            #pragma unroll
            for (int jj = 0; jj < 8; jj++) {
                int c = cq * 8 + jj;
                float v = o[jj] + sc2[c];
                #pragma unroll
                for (int j = 0; j < 8; j++) v = fmaf(m[j], sA2[j * HD + c], v);
                o[jj] = fmaxf(v, 0.f);
            }
            float* tr = &T[r * ASTRIDE + cq * 8];
            #pragma unroll
            for (int p = 0; p < 4; p++) *(float2*)(tr + p * 2) = make_float2(o[2*p], o[2*p+1]);
        }
    }
    __syncthreads();

    // ---- step3: outH = T @ Wf64 (unroll 4: doubled W-load MLP) ----
    {
        const ulonglong2* Wv = (const ulonglong2*)Wf64;
        u64 acc[4][2];
        #pragma unroll
        for (int i = 0; i < 4; i++) { acc[i][0] = 0ULL; acc[i][1] = 0ULL; }
        #pragma unroll 4
        for (int k = 0; k < 128; k += 2) {
            ulonglong2 wA = Wv[k * 16 + cq];
            ulonglong2 wB = Wv[(k + 1) * 16 + cq];
            #pragma unroll
            for (int i = 0; i < 4; i++) {
                float2 a2 = *(const float2*)&T[(rg + i * 16) * ASTRIDE + k];
                u64 aa0 = f2pack(a2.x), aa1 = f2pack(a2.y);
                acc[i][0] = f2fma(aa0, wA.x, acc[i][0]);
                acc[i][1] = f2fma(aa0, wA.y, acc[i][1]);
                acc[i][0] = f2fma(aa1, wB.x, acc[i][0]);
                acc[i][1] = f2fma(aa1, wB.y, acc[i][1]);
            }
        }
        const int c0 = cq * 4;
        #pragma unroll
        for (int i = 0; i < 4; i++) {
            int gr = row0 + rg + i * 16;
            if (gr >= N) continue;
            float o[4];
            f2unpack(acc[i][0], o[0], o[1]);
            f2unpack(acc[i][1], o[2], o[3]);
            *(float4*)(outH + gr * 64 + c0) = make_float4(o[0], o[1], o[2], o[3]);
        }
    }
}

// ---------------- fused gather + user-term + classifier: 1 warp/user ----------------
__global__ void __launch_bounds__(256) gather_cls_kernel(
    const float* __restrict__ xu, const float* __restrict__ AU, const float* __restrict__ cU,
    const float* __restrict__ pcH, const float* __restrict__ urlH,
    const int* __restrict__ offP, const int* __restrict__ adjP,
    const int* __restrict__ offR, const int* __restrict__ adjR,
    const float* __restrict__ Wc2, const float* __restrict__ bc2,
    float* __restrict__ out, int N)
{
    __shared__ float sAU[6 * 64];
    __shared__ float scU[64];
    __shared__ float sW2[128];
    int tid = threadIdx.x;                    // 256 = 8 warps = 8 users
    for (int i = tid; i < 384; i += 256) sAU[i] = AU[i];
    if (tid < 64) scU[tid] = cU[tid];
    if (tid >= 64 && tid < 192) sW2[tid - 64] = Wc2[tid - 64];
    __syncthreads();

    int w = tid >> 5, lane = tid & 31;
    int u = blockIdx.x * 8 + w;
    if (u >= N) return;
    int c0 = lane * 2;

    float a0 = scU[c0], a1 = scU[c0 + 1];
    #pragma unroll
    for (int j = 0; j < 6; j++) {
        float xv = __ldg(&xu[u * 6 + j]);
        a0 = fmaf(xv, sAU[j * 64 + c0], a0);
        a1 = fmaf(xv, sAU[j * 64 + c0 + 1], a1);
    }
    {
        int e = offP[u], end = offP[u + 1];
        for (; e + 2 <= end; e += 2) {
            int i0 = adjP[e], i1 = adjP[e + 1];
            float2 v0 = *(const float2*)&pcH[i0 * 64 + c0];
            float2 v1 = *(const float2*)&pcH[i1 * 64 + c0];
            a0 += v0.x + v1.x;
            a1 += v0.y + v1.y;
        }
        if (e < end) {
            float2 v = *(const float2*)&pcH[adjP[e] * 64 + c0];
            a0 += v.x; a1 += v.y;
        }
    }
    {
        int e = offR[u], end = offR[u + 1];
        for (; e + 4 <= end; e += 4) {
            int i0 = adjR[e], i1 = adjR[e + 1], i2 = adjR[e + 2], i3 = adjR[e + 3];
            float2 v0 = *(const float2*)&urlH[i0 * 64 + c0];
            float2 v1 = *(const float2*)&urlH[i1 * 64 + c0];
            float2 v2 = *(const float2*)&urlH[i2 * 64 + c0];
            float2 v3 = *(const float2*)&urlH[i3 * 64 + c0];
            a0 += (v0.x + v1.x) + (v2.x + v3.x);
            a1 += (v0.y + v1.y) + (v2.y + v3.y);
        }
        for (; e < end; e++) {
            float2 v = *(const float2*)&urlH[adjR[e] * 64 + c0];
            a0 += v.x; a1 += v.y;
        }
    }
    float h0 = fmaxf(a0, 0.f), h1 = fmaxf(a1, 0.f);
    float p0 = fmaf(h0, sW2[c0 * 2],     h1 * sW2[(c0 + 1) * 2]);
    float p1 = fmaf(h0, sW2[c0 * 2 + 1], h1 * sW2[(c0 + 1) * 2 + 1]);
    #pragma unroll
    for (int o = 16; o > 0; o >>= 1) {
        p0 += __shfl_down_sync(0xffffffffu, p0, o);
        p1 += __shfl_down_sync(0xffffffffu, p1, o);
    }
    if (lane == 0) {
        out[u * 2 + 0] = p0 + bc2[0];
        out[u * 2 + 1] = p1 + bc2[1];
    }
}

// ---------------- streams/events (static init) ----------------
struct StreamCtx {
    cudaStream_t s1, s2, s3;
    cudaEvent_t evRoot, evPrep, evPC, evURL;
    StreamCtx() {
        cudaStreamCreateWithFlags(&s1, cudaStreamNonBlocking);
        cudaStreamCreateWithFlags(&s2, cudaStreamNonBlocking);
        cudaStreamCreateWithFlags(&s3, cudaStreamNonBlocking);
        cudaEventCreateWithFlags(&evRoot, cudaEventDisableTiming);
        cudaEventCreateWithFlags(&evPrep, cudaEventDisableTiming);
        cudaEventCreateWithFlags(&evPC,   cudaEventDisableTiming);
        cudaEventCreateWithFlags(&evURL,  cudaEventDisableTiming);
    }
};
static StreamCtx g_sc;

// ---------------- host orchestration ----------------
#define SYMADDR(p, s) do { void* _t; cudaGetSymbolAddress(&_t, s); p = (decltype(p))_t; } while (0)

extern "C" void kernel_launch(void* const* d_in, const int* in_sizes, int n_in,
                              void* d_out, int out_size) {
    const float* x_user = (const float*)d_in[0];
    const float* x_pc   = (const float*)d_in[1];
    const float* x_url  = (const float*)d_in[2];
    const int* up_src   = (const int*)d_in[3];
    const int* up_dst   = (const int*)d_in[4];
    const int* uu_src   = (const int*)d_in[5];
    const int* uu_dst   = (const int*)d_in[6];
    const float* Wu = (const float*)d_in[7];
    const float* bu = (const float*)d_in[8];
    const float* Wp = (const float*)d_in[9];
    const float* bp = (const float*)d_in[10];
    const float* Wrf = (const float*)d_in[11];
    const float* brf = (const float*)d_in[12];
    const float* Wl_pc = (const float*)d_in[13];
    const float* bl_pc = (const float*)d_in[14];
    const float* Wr_pc = (const float*)d_in[15];
    const float* Wl_url = (const float*)d_in[16];
    const float* bl_url = (const float*)d_in[17];
    const float* Wr_url = (const float*)d_in[18];
    const float* Wctx = (const float*)d_in[19];
    const float* bctx = (const float*)d_in[20];
    const float* Wc1 = (const float*)d_in[21];
    const float* bc1 = (const float*)d_in[22];
    const float* Wc2 = (const float*)d_in[23];
    const float* bc2 = (const float*)d_in[24];
    float* out = (float*)d_out;

    float *mx_pc, *mx_url, *pcH, *urlH;
    float *Wf, *W2pc, *W2url, *A1pc, *A2pc, *A1url, *A2url, *B1pc, *c1pc, *B1url, *c1url, *AU, *cU;
    SYMADDR(mx_pc, g_mx_pc); SYMADDR(mx_url, g_mx_url);
    SYMADDR(pcH, g_pcH); SYMADDR(urlH, g_urlH);
    SYMADDR(Wf, g_Wf); SYMADDR(W2pc, g_W2pc); SYMADDR(W2url, g_W2url);
    SYMADDR(A1pc, g_A1pc); SYMADDR(A2pc, g_A2pc); SYMADDR(A1url, g_A1url); SYMADDR(A2url, g_A2url);
    SYMADDR(B1pc, g_B1pc); SYMADDR(c1pc, g_c1pc); SYMADDR(B1url, g_B1url); SYMADDR(c1url, g_c1url);
    SYMADDR(AU, g_AU); SYMADDR(cU, g_cU);

    int *cnt_ups, *off_ups, *cur_ups, *adj_ups;
    int *cnt_uus, *off_uus, *cur_uus, *adj_uus;
    SYMADDR(cnt_ups, g_cnt_ups); SYMADDR(off_ups, g_off_ups); SYMADDR(cur_ups, g_cur_ups); SYMADDR(adj_ups, g_adj_ups);
    SYMADDR(cnt_uus, g_cnt_uus); SYMADDR(off_uus, g_off_uus); SYMADDR(cur_uus, g_cur_uus); SYMADDR(adj_uus, g_adj_uus);

    const int SAGE_SMEM = (64 * ASTRIDE + 8 * HD * 2 + 4 * HD + 2 * HD + 64 * 8 + 64 * 4) * 4;  // 48128 B
    cudaFuncSetAttribute(sage_fused, cudaFuncAttributeMaxDynamicSharedMemorySize, SAGE_SMEM);

    cudaStream_t s0 = 0;
    cudaStream_t s1 = g_sc.s1, s2 = g_sc.s2, s3 = g_sc.s3;

    // ---- fork ----
    cudaEventRecord(g_sc.evRoot, s0);
    cudaStreamWaitEvent(s1, g_sc.evRoot, 0);
    cudaStreamWaitEvent(s2, g_sc.evRoot, 0);
    cudaStreamWaitEvent(s3, g_sc.evRoot, 0);

    // ---- s3: weight folding ----
    prep_kernel<<<73, 256, 0, s3>>>(Wctx, Wc1, Wu, bu, Wp, bp, Wrf, brf,
                                    Wl_pc, Wr_pc, bl_pc, Wl_url, Wr_url, bl_url,
                                    bctx, bc1,
                                    Wf, W2pc, W2url, A1pc, A2pc, A1url, A2url,
                                    B1pc, c1pc, B1url, c1url, AU, cU);
    cudaEventRecord(g_sc.evPrep, s3);

    // ---- s2: url chain (own accum -> own sage) ----
    cudaMemsetAsync(mx_url, 0, NURL * 8 * sizeof(float), s2);
    accum_kernel<<<(EUU + 255) / 256, 256, 0, s2>>>(x_user, uu_src, uu_dst, EUU, mx_url);
    cudaStreamWaitEvent(s2, g_sc.evPrep, 0);
    sage_fused<<<(NURL + 63) / 64, 256, SAGE_SMEM, s2>>>(x_url, 3, mx_url,
                                                         A1url, B1url, c1url,
                                                         A2url, W2url, bl_url + HD,
                                                         Wf + HD * 64, urlH, NURL);
    cudaEventRecord(g_sc.evURL, s2);

    // ---- s1: pc chain (own accum -> own sage) ----
    cudaMemsetAsync(mx_pc, 0, NPC * 8 * sizeof(float), s1);
    accum_kernel<<<(EUP + 255) / 256, 256, 0, s1>>>(x_user, up_src, up_dst, EUP, mx_pc);
    cudaStreamWaitEvent(s1, g_sc.evPrep, 0);
    sage_fused<<<(NPC + 63) / 64, 256, SAGE_SMEM, s1>>>(x_pc, 4, mx_pc,
                                                        A1pc, B1pc, c1pc,
                                                        A2pc, W2pc, bl_pc + HD,
                                                        Wf, pcH, NPC);
    cudaEventRecord(g_sc.evPC, s1);

    // ---- s0: src-side CSR (overlapped) ----
    cudaMemsetAsync(cnt_ups, 0, NU * sizeof(int), s0);
    cudaMemsetAsync(cnt_uus, 0, NU * sizeof(int), s0);
    count2_kernel<<<(EUP + EUU + 255) / 256, 256, 0, s0>>>(up_src, uu_src, cnt_ups, cnt_uus);
    SetDesc d2{cnt_ups, off_ups, cur_ups, NU};
    SetDesc d3{cnt_uus, off_uus, cur_uus, NU};
    dim3 gScan((NU + 1023) / 1024, 2);
    scanA_kernel<<<gScan, 256, 0, s0>>>(d2, d3);
    scanB_kernel<<<2, 128, 0, s0>>>(d2, d3);
    scanC_kernel<<<gScan, 256, 0, s0>>>(d2, d3);
    fill2_kernel<<<(EUP + EUU + 255) / 256, 256, 0, s0>>>(up_src, up_dst, uu_src, uu_dst,
                                                          cur_ups, adj_ups, cur_uus, adj_uus);

    // ---- join on s0: fused gather + classifier ----
    cudaStreamWaitEvent(s0, g_sc.evPC, 0);
    cudaStreamWaitEvent(s0, g_sc.evURL, 0);
    gather_cls_kernel<<<(NU + 7) / 8, 256, 0, s0>>>(x_user, AU, cU, pcH, urlH,
                                                    off_ups, adj_ups, off_uus, adj_uus,
                                                    Wc2, bc2, out, NU);
}

// round 16
// speedup vs baseline: 1.1099x; 1.0078x over previous
#include <cuda_runtime.h>
#include <cstdint>

#define NU   100000
#define NPC  20000
#define NURL 50000
#define EUP  250000
#define EUU  500000
#define HD   128
#define MAXB 128
#define ASTRIDE 132

// ---------------- scratch ----------------
__device__ __align__(16) float g_mx_pc[NPC*8];    // cols 0..5 sum, 6 count, 7 zero
__device__ __align__(16) float g_mx_url[NURL*8];
__device__ __align__(16) float g_pcH[NPC*64];
__device__ __align__(16) float g_urlH[NURL*64];

// folded weights
__device__ __align__(16) float g_Wf[2*HD*64];     // WfP | WfR
__device__ __align__(16) float g_W2pc[HD*HD];
__device__ __align__(16) float g_W2url[HD*HD];
__device__ __align__(16) float g_A1pc[8*HD];
__device__ __align__(16) float g_A2pc[8*HD];
__device__ __align__(16) float g_A1url[8*HD];
__device__ __align__(16) float g_A2url[8*HD];
__device__ __align__(16) float g_B1pc[4*HD];
__device__ __align__(16) float g_c1pc[HD];
__device__ __align__(16) float g_B1url[4*HD];     // padded to 4 rows (row 3 zero for url)
__device__ __align__(16) float g_c1url[HD];
__device__ __align__(16) float g_AU[6*64];
__device__ __align__(16) float g_cU[64];

// src-side CSR (for gather_cls)
__device__ __align__(16) int g_cnt_ups[NU];  __device__ int g_off_ups[NU+1];  __device__ int g_cur_ups[NU];  __device__ int g_adj_ups[EUP];
__device__ __align__(16) int g_cnt_uus[NU];  __device__ int g_off_uus[NU+1];  __device__ int g_cur_uus[NU];  __device__ int g_adj_uus[EUU];
__device__ int g_part[2*MAXB];

// ---------------- f32x2 helpers ----------------
typedef unsigned long long u64;
__device__ __forceinline__ u64 f2fma(u64 a, u64 b, u64 c) {
    u64 d; asm("fma.rn.f32x2 %0, %1, %2, %3;" : "=l"(d) : "l"(a), "l"(b), "l"(c)); return d;
}
__device__ __forceinline__ u64 f2pack(float x) {
    u64 r; asm("mov.b64 %0, {%1, %1};" : "=l"(r) : "f"(x)); return r;
}
__device__ __forceinline__ void f2unpack(u64 v, float& x, float& y) {
    asm("mov.b64 {%0, %1}, %2;" : "=f"(x), "=f"(y) : "l"(v));
}
__device__ __forceinline__ void red_v4(float* p, float a, float b, float c, float d) {
    asm volatile("red.global.add.v4.f32 [%0], {%1, %2, %3, %4};"
                 :: "l"(p), "f"(a), "f"(b), "f"(c), "f"(d) : "memory");
}

// ---------------- per-type edge-parallel mx accumulation ----------------
__global__ void accum_kernel(const float* __restrict__ xu,
                             const int* __restrict__ src, const int* __restrict__ dst,
                             int E, float* __restrict__ mx) {
    int i = blockIdx.x * blockDim.x + threadIdx.x;
    if (i >= E) return;
    int s = src[i], d = dst[i];
    const float2* xr = (const float2*)(xu + s * 6);
    float2 a = xr[0], b = xr[1], c = xr[2];
    float* m = mx + d * 8;
    red_v4(m,     a.x, a.y, b.x, b.y);
    red_v4(m + 4, c.x, c.y, 1.f, 0.f);
}

// ---------------- src-side CSR ----------------
__global__ void count2_kernel(const int* __restrict__ up_src, const int* __restrict__ uu_src,
                              int* cntP, int* cntU) {
    int i = blockIdx.x * blockDim.x + threadIdx.x;
    if (i < EUP) atomicAdd(&cntP[up_src[i]], 1);
    else {
        int e = i - EUP;
        if (e < EUU) atomicAdd(&cntU[uu_src[e]], 1);
    }
}

struct SetDesc { const int* cnt; int* off; int* cur; int n; };

__global__ void scanA_kernel(SetDesc s0, SetDesc s1) {
    SetDesc s = (blockIdx.y == 0) ? s0 : s1;
    int nb = (s.n + 1023) >> 10;
    if ((int)blockIdx.x >= nb) return;
    int tid = threadIdx.x;
    int i = blockIdx.x * 1024 + tid * 4;
    int sum = 0;
    #pragma unroll
    for (int j = 0; j < 4; j++) { int idx = i + j; if (idx < s.n) sum += s.cnt[idx]; }
    #pragma unroll
    for (int o = 16; o > 0; o >>= 1) sum += __shfl_down_sync(0xffffffffu, sum, o);
    __shared__ int ws[8];
    if ((tid & 31) == 0) ws[tid >> 5] = sum;
    __syncthreads();
    if (tid < 8) {
        int v = ws[tid];
        #pragma unroll
        for (int o = 4; o > 0; o >>= 1) v += __shfl_down_sync(0xffu, v, o);
        if (tid == 0) g_part[blockIdx.y * MAXB + blockIdx.x] = v;
    }
}

__global__ void scanB_kernel(SetDesc s0, SetDesc s1) {
    SetDesc s = (blockIdx.x == 0) ? s0 : s1;
    int nb = (s.n + 1023) >> 10;
    int tid = threadIdx.x;
    int v = (tid < nb) ? g_part[blockIdx.x * MAXB + tid] : 0;
    int lane = tid & 31, w = tid >> 5;
    int x = v;
    #pragma unroll
    for (int o = 1; o < 32; o <<= 1) { int y = __shfl_up_sync(0xffffffffu, x, o); if (lane >= o) x += y; }
    __shared__ int wt[4];
    if (lane == 31) wt[w] = x;
    __syncthreads();
    int add = 0;
    for (int j = 0; j < w; j++) add += wt[j];
    int incl = x + add;
    if (tid < nb) g_part[blockIdx.x * MAXB + tid] = incl - v;
    if (tid == 127) s.off[s.n] = incl;
}

__global__ void scanC_kernel(SetDesc s0, SetDesc s1) {
    SetDesc s = (blockIdx.y == 0) ? s0 : s1;
    int nb = (s.n + 1023) >> 10;
    if ((int)blockIdx.x >= nb) return;
    int tid = threadIdx.x;
    int base = g_part[blockIdx.y * MAXB + blockIdx.x];
    int i = blockIdx.x * 1024 + tid * 4;
    int v0 = 0, v1 = 0, v2 = 0, v3 = 0;
    if (i     < s.n) v0 = s.cnt[i];
    if (i + 1 < s.n) v1 = s.cnt[i + 1];
    if (i + 2 < s.n) v2 = s.cnt[i + 2];
    if (i + 3 < s.n) v3 = s.cnt[i + 3];
    int sv = v0 + v1 + v2 + v3;
    int lane = tid & 31, w = tid >> 5;
    int x = sv;
    #pragma unroll
    for (int o = 1; o < 32; o <<= 1) { int y = __shfl_up_sync(0xffffffffu, x, o); if (lane >= o) x += y; }
    __shared__ int wt[8];
    if (lane == 31) wt[w] = x;
    __syncthreads();
    int add = base;
    for (int j = 0; j < w; j++) add += wt[j];
    int e0 = add + x - sv;
    int e1 = e0 + v0, e2 = e1 + v1, e3 = e2 + v2;
    if (i     < s.n) { s.off[i]     = e0; s.cur[i]     = e0; }
    if (i + 1 < s.n) { s.off[i + 1] = e1; s.cur[i + 1] = e1; }
    if (i + 2 < s.n) { s.off[i + 2] = e2; s.cur[i + 2] = e2; }
    if (i + 3 < s.n) { s.off[i + 3] = e3; s.cur[i + 3] = e3; }
}

__global__ void fill2_kernel(const int* __restrict__ up_src, const int* __restrict__ up_dst,
                             const int* __restrict__ uu_src, const int* __restrict__ uu_dst,
                             int* curP, int* adjP, int* curU, int* adjU) {
    int i = blockIdx.x * blockDim.x + threadIdx.x;
    if (i < EUP) {
        adjP[atomicAdd(&curP[up_src[i]], 1)] = up_dst[i];
    } else {
        int e = i - EUP;
        if (e < EUU) adjU[atomicAdd(&curU[uu_src[e]], 1)] = uu_dst[e];
    }
}

// ---------------- prep: fold all weights (single kernel, 73 blocks) ----------------
__global__ void prep_kernel(const float* __restrict__ Wctx, const float* __restrict__ Wc1,
                            const float* __restrict__ Wu, const float* __restrict__ bu,
                            const float* __restrict__ Wp, const float* __restrict__ bp,
                            const float* __restrict__ Wrf, const float* __restrict__ brf,
                            const float* __restrict__ Wl_pc, const float* __restrict__ Wr_pc,
                            const float* __restrict__ bl_pc,
                            const float* __restrict__ Wl_url, const float* __restrict__ Wr_url,
                            const float* __restrict__ bl_url,
                            const float* __restrict__ bctx, const float* __restrict__ bc1,
                            float* __restrict__ Wf, float* __restrict__ W2pc, float* __restrict__ W2url,
                            float* __restrict__ A1pc, float* __restrict__ A2pc,
                            float* __restrict__ A1url, float* __restrict__ A2url,
                            float* __restrict__ B1pc, float* __restrict__ c1pc,
                            float* __restrict__ B1url, float* __restrict__ c1url,
                            float* __restrict__ AU, float* __restrict__ cU)
{
    int b = blockIdx.x;
    int tid = threadIdx.x;                       // 256
    if (b < 64) {
        __shared__ float sWc1[HD * 64];
        for (int i = tid; i < HD * 64; i += 256) sWc1[i] = Wc1[i];
        __syncthreads();
        int seg = 1 + (b >> 5);
        int r = (b & 31) * 4 + (tid >> 6);
        int c = tid & 63;
        int j = seg * HD + r;
        float acc = 0.f;
        #pragma unroll 8
        for (int m = 0; m < HD; m++) acc = fmaf(Wctx[j * HD + m], sWc1[m * 64 + c], acc);
        Wf[((seg - 1) * HD + r) * 64 + c] = acc;
        return;
    }
    if (b == 64 || b == 65) {
        const float* Wr1 = (b == 64) ? (Wr_pc + HD * HD) : (Wr_url + HD * HD);
        float* W2 = (b == 64) ? W2pc : W2url;
        for (int i = tid; i < HD * HD; i += 256) {
            float v = Wr1[i];
            if ((i >> 7) == (i & 127)) v += 1.f;
            W2[i] = v;
        }
        return;
    }
    if (b >= 66 && b <= 69) {
        const float* Wl;
        float* A;
        if (b == 66)      { Wl = Wl_pc;            A = A1pc; }
        else if (b == 67) { Wl = Wl_pc + HD * HD;  A = A2pc; }
        else if (b == 68) { Wl = Wl_url;           A = A1url; }
        else              { Wl = Wl_url + HD * HD; A = A2url; }
        #pragma unroll
        for (int q = 0; q < 4; q++) {
            int idx = q * 256 + tid;
            int r = idx >> 7, c = idx & 127;
            float acc = 0.f;
            if (r < 6) {
                #pragma unroll 8
                for (int m = 0; m < HD; m++) acc = fmaf(Wu[r * HD + m], Wl[m * HD + c], acc);
            } else if (r == 6) {
                #pragma unroll 8
                for (int m = 0; m < HD; m++) acc = fmaf(bu[m], Wl[m * HD + c], acc);
            }
            A[idx] = acc;
        }
        return;
    }
    if (b == 70 || b == 71) {
        const float* Wsrc = (b == 70) ? Wp : Wrf;
        const float* bsrc = (b == 70) ? bp : brf;
        const float* Wr0  = (b == 70) ? Wr_pc : Wr_url;
        const float* bl0  = (b == 70) ? bl_pc : bl_url;
        float* B1 = (b == 70) ? B1pc : B1url;
        float* c1 = (b == 70) ? c1pc : c1url;
        int Kin = (b == 70) ? 4 : 3;
        int nB = Kin * HD;
        for (int idx = tid; idx < 4 * HD + HD; idx += 256) {
            if (idx < nB) {
                int r = idx / HD, c = idx % HD;
                float acc = 0.f;
                #pragma unroll 8
                for (int m = 0; m < HD; m++) acc = fmaf(Wsrc[r * HD + m], Wr0[m * HD + c], acc);
                B1[idx] = acc;
            } else if (idx < 4 * HD) {
                B1[idx] = 0.f;                        // pad row(s) zero
            } else {
                int c = idx - 4 * HD;
                float acc = bl0[c];
                #pragma unroll 8
                for (int m = 0; m < HD; m++) acc = fmaf(bsrc[m], Wr0[m * HD + c], acc);
                c1[c] = acc;
            }
        }
        return;
    }
    // b == 72: AU = (Wu @ Wctx_U) @ Wc1 ; cU = (bu@Wctx_U + bctx)@Wc1 + bc1
    {
        __shared__ float tmp[7 * HD];
        for (int idx = tid; idx < 7 * HD; idx += 256) {
            int j = idx >> 7, m = idx & 127;
            float acc = 0.f;
            if (j < 6) {
                #pragma unroll 8
                for (int r = 0; r < HD; r++) acc = fmaf(Wu[j * HD + r], Wctx[r * HD + m], acc);
            } else {
                acc = bctx[m];
                #pragma unroll 8
                for (int r = 0; r < HD; r++) acc = fmaf(bu[r], Wctx[r * HD + m], acc);
            }
            tmp[idx] = acc;
        }
        __syncthreads();
        for (int idx = tid; idx < 7 * 64; idx += 256) {
            int j = idx / 64, c = idx % 64;
            float acc = (j == 6) ? bc1[c] : 0.f;
            #pragma unroll 8
            for (int m = 0; m < HD; m++) acc = fmaf(tmp[j * HD + m], Wc1[m * 64 + c], acc);
            if (j < 6) AU[j * 64 + c] = acc;
            else       cU[c] = acc;
        }
    }
}

// ---------------- fused SAGE chain: 64-row tiles, 3 CTAs/SM ----------------
__global__ void __launch_bounds__(256, 3) sage_fused(
    const float* __restrict__ xf, int Kin, const float* __restrict__ mx,
    const float* __restrict__ A1, const float* __restrict__ B1, const float* __restrict__ c1,
    const float* __restrict__ A2, const float* __restrict__ W2, const float* __restrict__ c2,
    const float* __restrict__ Wf64, float* __restrict__ outH, int N)
{
    extern __shared__ float smem[];
    float* T   = smem;                      // [64][ASTRIDE]
    float* sA1 = T + 64 * ASTRIDE;          // 1024
    float* sA2 = sA1 + 8 * HD;              // 1024
    float* sB1 = sA2 + 8 * HD;              // 512 (4 rows, padded)
    float* sc1 = sB1 + 4 * HD;              // 128
    float* sc2 = sc1 + HD;                  // 128
    float* smx = sc2 + HD;                  // 64*8
    float* sxf = smx + 64 * 8;              // 64*4

    const int tid = threadIdx.x;
    const int cq = tid & 15;
    const int rg = tid >> 4;
    const int row0 = blockIdx.x * 64;

    // ---- stage (vectorized; disjoint regions) ----
    ((float4*)sA1)[tid] = ((const float4*)A1)[tid];        // 1024 floats
    ((float4*)sA2)[tid] = ((const float4*)A2)[tid];
    if (tid < 128) {
        ((float4*)sB1)[tid] = ((const float4*)B1)[tid];    // 512 floats (padded rows)
        sc1[tid] = c1[tid];
        sc2[tid] = c2[tid];
    }
    if (tid < 64) {                                        // one mx row each, normalized
        int gr = row0 + tid;
        float4 m0 = make_float4(0.f, 0.f, 0.f, 0.f);
        float4 m1 = make_float4(0.f, 0.f, 0.f, 0.f);
        if (gr < N) {
            m0 = ((const float4*)mx)[gr * 2];
            m1 = ((const float4*)mx)[gr * 2 + 1];
        }
        float cnt = m1.z;
        float inv = (cnt > 0.f) ? (1.f / cnt) : 0.f;
        m0.x *= inv; m0.y *= inv; m0.z *= inv; m0.w *= inv;
        m1.x *= inv; m1.y *= inv;
        m1.z = (cnt > 0.f) ? 1.f : 0.f;
        m1.w = 0.f;
        ((float4*)smx)[tid * 2]     = m0;
        ((float4*)smx)[tid * 2 + 1] = m1;
    }
    {                                                      // sxf: 64 rows x 4 (padded) = 256 entries
        int r = tid >> 2, j = tid & 3;
        int gr = row0 + r;
        sxf[tid] = (gr < N && j < Kin) ? xf[gr * Kin + j] : 0.f;
    }
    __syncthreads();

    // ---- step1: T = relu(mx@A1 + xf@B1(4 padded rows) + c1) ----
    #pragma unroll
    for (int i = 0; i < 4; i++) {
        int r = rg + i * 16;
        float m[8];
        #pragma unroll
        for (int j = 0; j < 8; j++) m[j] = smx[r * 8 + j];
        float xr[4];
        #pragma unroll
        for (int j = 0; j < 4; j++) xr[j] = sxf[r * 4 + j];
        float o[8];
        #pragma unroll
        for (int jj = 0; jj < 8; jj++) {
            int c = cq * 8 + jj;
            float v = sc1[c];
            #pragma unroll
            for (int j = 0; j < 8; j++) v = fmaf(m[j], sA1[j * HD + c], v);
            #pragma unroll
            for (int j = 0; j < 4; j++) v = fmaf(xr[j], sB1[j * HD + c], v);
            o[jj] = fmaxf(v, 0.f);
        }
        float* tr = &T[r * ASTRIDE + cq * 8];
        #pragma unroll
        for (int p = 0; p < 4; p++) *(float2*)(tr + p * 2) = make_float2(o[2*p], o[2*p+1]);
    }
    __syncthreads();

    // ---- step2: acc = T@W2 (regs), then T <- relu(acc + mx@A2 + c2) ----
    {
        const ulonglong2* W2v = (const ulonglong2*)W2;
        u64 acc[4][4];
        #pragma unroll
        for (int i = 0; i < 4; i++)
            #pragma unroll
            for (int p = 0; p < 4; p++) acc[i][p] = 0ULL;
        #pragma unroll 4
        for (int k = 0; k < 128; k += 2) {
            ulonglong2 w10a = W2v[k * 32 + cq * 2];
            ulonglong2 w10b = W2v[k * 32 + cq * 2 + 1];
            ulonglong2 w11a = W2v[(k + 1) * 32 + cq * 2];
            ulonglong2 w11b = W2v[(k + 1) * 32 + cq * 2 + 1];
            #pragma unroll
            for (int i = 0; i < 4; i++) {
                float2 a2 = *(const float2*)&T[(rg + i * 16) * ASTRIDE + k];
                u64 aa0 = f2pack(a2.x), aa1 = f2pack(a2.y);
                acc[i][0] = f2fma(aa0, w10a.x, acc[i][0]);
                acc[i][1] = f2fma(aa0, w10a.y, acc[i][1]);
                acc[i][2] = f2fma(aa0, w10b.x, acc[i][2]);
                acc[i][3] = f2fma(aa0, w10b.y, acc[i][3]);
                acc[i][0] = f2fma(aa1, w11a.x, acc[i][0]);
                acc[i][1] = f2fma(aa1, w11a.y, acc[i][1]);
                acc[i][2] = f2fma(aa1, w11b.x, acc[i][2]);
                acc[i][3] = f2fma(aa1, w11b.y, acc[i][3]);
            }
        }
        __syncthreads();   // all T reads complete before overwrite
        #pragma unroll
        for (int i = 0; i < 4; i++) {
            int r = rg + i * 16;
            float o[8];
            f2unpack(acc[i][0], o[0], o[1]);
            f2unpack(acc[i][1], o[2], o[3]);
            f2unpack(acc[i][2], o[4], o[5]);
            f2unpack(acc[i][3], o[6], o[7]);
            float m[8];
            #pragma unroll
            for (int j = 0; j < 8; j++) m[j] = smx[r * 8 + j];
            #pragma unroll
            for (int jj = 0; jj < 8; jj++) {
                int c = cq * 8 + jj;
                float v = o[jj] + sc2[c];
                #pragma unroll
                for (int j = 0; j < 8; j++) v = fmaf(m[j], sA2[j * HD + c], v);
                o[jj] = fmaxf(v, 0.f);
            }
            float* tr = &T[r * ASTRIDE + cq * 8];
            #pragma unroll
            for (int p = 0; p < 4; p++) *(float2*)(tr + p * 2) = make_float2(o[2*p], o[2*p+1]);
        }
    }
    __syncthreads();

    // ---- step3: outH = T @ Wf64 (unroll 4) ----
    {
        const ulonglong2* Wv = (const ulonglong2*)Wf64;
        u64 acc[4][2];
        #pragma unroll
        for (int i = 0; i < 4; i++) { acc[i][0] = 0ULL; acc[i][1] = 0ULL; }
        #pragma unroll 4
        for (int k = 0; k < 128; k += 2) {
            ulonglong2 wA = Wv[k * 16 + cq];
            ulonglong2 wB = Wv[(k + 1) * 16 + cq];
            #pragma unroll
            for (int i = 0; i < 4; i++) {
                float2 a2 = *(const float2*)&T[(rg + i * 16) * ASTRIDE + k];
                u64 aa0 = f2pack(a2.x), aa1 = f2pack(a2.y);
                acc[i][0] = f2fma(aa0, wA.x, acc[i][0]);
                acc[i][1] = f2fma(aa0, wA.y, acc[i][1]);
                acc[i][0] = f2fma(aa1, wB.x, acc[i][0]);
                acc[i][1] = f2fma(aa1, wB.y, acc[i][1]);
            }
        }
        const int c0 = cq * 4;
        #pragma unroll
        for (int i = 0; i < 4; i++) {
            int gr = row0 + rg + i * 16;
            if (gr >= N) continue;
            float o[4];
            f2unpack(acc[i][0], o[0], o[1]);
            f2unpack(acc[i][1], o[2], o[3]);
            *(float4*)(outH + gr * 64 + c0) = make_float4(o[0], o[1], o[2], o[3]);
        }
    }
}

// ---------------- fused gather + user-term + classifier: 1 warp/user ----------------
__global__ void __launch_bounds__(256) gather_cls_kernel(
    const float* __restrict__ xu, const float* __restrict__ AU, const float* __restrict__ cU,
    const float* __restrict__ pcH, const float* __restrict__ urlH,
    const int* __restrict__ offP, const int* __restrict__ adjP,
    const int* __restrict__ offR, const int* __restrict__ adjR,
    const float* __restrict__ Wc2, const float* __restrict__ bc2,
    float* __restrict__ out, int N)
{
    __shared__ float sAU[6 * 64];
    __shared__ float scU[64];
    __shared__ float sW2[128];
    int tid = threadIdx.x;                    // 256 = 8 warps = 8 users
    for (int i = tid; i < 384; i += 256) sAU[i] = AU[i];
    if (tid < 64) scU[tid] = cU[tid];
    if (tid >= 64 && tid < 192) sW2[tid - 64] = Wc2[tid - 64];
    __syncthreads();

    int w = tid >> 5, lane = tid & 31;
    int u = blockIdx.x * 8 + w;
    if (u >= N) return;
    int c0 = lane * 2;

    float a0 = scU[c0], a1 = scU[c0 + 1];
    #pragma unroll
    for (int j = 0; j < 6; j++) {
        float xv = __ldg(&xu[u * 6 + j]);
        a0 = fmaf(xv, sAU[j * 64 + c0], a0);
        a1 = fmaf(xv, sAU[j * 64 + c0 + 1], a1);
    }
    {
        int e = offP[u], end = offP[u + 1];
        for (; e + 2 <= end; e += 2) {
            int i0 = adjP[e], i1 = adjP[e + 1];
            float2 v0 = *(const float2*)&pcH[i0 * 64 + c0];
            float2 v1 = *(const float2*)&pcH[i1 * 64 + c0];
            a0 += v0.x + v1.x;
            a1 += v0.y + v1.y;
        }
        if (e < end) {
            float2 v = *(const float2*)&pcH[adjP[e] * 64 + c0];
            a0 += v.x; a1 += v.y;
        }
    }
    {
        int e = offR[u], end = offR[u + 1];
        for (; e + 4 <= end; e += 4) {
            int i0 = adjR[e], i1 = adjR[e + 1], i2 = adjR[e + 2], i3 = adjR[e + 3];
            float2 v0 = *(const float2*)&urlH[i0 * 64 + c0];
            float2 v1 = *(const float2*)&urlH[i1 * 64 + c0];
            float2 v2 = *(const float2*)&urlH[i2 * 64 + c0];
            float2 v3 = *(const float2*)&urlH[i3 * 64 + c0];
            a0 += (v0.x + v1.x) + (v2.x + v3.x);
            a1 += (v0.y + v1.y) + (v2.y + v3.y);
        }
        for (; e < end; e++) {
            float2 v = *(const float2*)&urlH[adjR[e] * 64 + c0];
            a0 += v.x; a1 += v.y;
        }
    }
    float h0 = fmaxf(a0, 0.f), h1 = fmaxf(a1, 0.f);
    float p0 = fmaf(h0, sW2[c0 * 2],     h1 * sW2[(c0 + 1) * 2]);
    float p1 = fmaf(h0, sW2[c0 * 2 + 1], h1 * sW2[(c0 + 1) * 2 + 1]);
    #pragma unroll
    for (int o = 16; o > 0; o >>= 1) {
        p0 += __shfl_down_sync(0xffffffffu, p0, o);
        p1 += __shfl_down_sync(0xffffffffu, p1, o);
    }
    if (lane == 0) {
        out[u * 2 + 0] = p0 + bc2[0];
        out[u * 2 + 1] = p1 + bc2[1];
    }
}

// ---------------- streams/events (static init) ----------------
struct StreamCtx {
    cudaStream_t s1, s2, s3;
    cudaEvent_t evRoot, evPrep, evPC, evURL;
    StreamCtx() {
        cudaStreamCreateWithFlags(&s1, cudaStreamNonBlocking);
        cudaStreamCreateWithFlags(&s2, cudaStreamNonBlocking);
        cudaStreamCreateWithFlags(&s3, cudaStreamNonBlocking);
        cudaEventCreateWithFlags(&evRoot, cudaEventDisableTiming);
        cudaEventCreateWithFlags(&evPrep, cudaEventDisableTiming);
        cudaEventCreateWithFlags(&evPC,   cudaEventDisableTiming);
        cudaEventCreateWithFlags(&evURL,  cudaEventDisableTiming);
    }
};
static StreamCtx g_sc;

// ---------------- host orchestration ----------------
#define SYMADDR(p, s) do { void* _t; cudaGetSymbolAddress(&_t, s); p = (decltype(p))_t; } while (0)

extern "C" void kernel_launch(void* const* d_in, const int* in_sizes, int n_in,
                              void* d_out, int out_size) {
    const float* x_user = (const float*)d_in[0];
    const float* x_pc   = (const float*)d_in[1];
    const float* x_url  = (const float*)d_in[2];
    const int* up_src   = (const int*)d_in[3];
    const int* up_dst   = (const int*)d_in[4];
    const int* uu_src   = (const int*)d_in[5];
    const int* uu_dst   = (const int*)d_in[6];
    const float* Wu = (const float*)d_in[7];
    const float* bu = (const float*)d_in[8];
    const float* Wp = (const float*)d_in[9];
    const float* bp = (const float*)d_in[10];
    const float* Wrf = (const float*)d_in[11];
    const float* brf = (const float*)d_in[12];
    const float* Wl_pc = (const float*)d_in[13];
    const float* bl_pc = (const float*)d_in[14];
    const float* Wr_pc = (const float*)d_in[15];
    const float* Wl_url = (const float*)d_in[16];
    const float* bl_url = (const float*)d_in[17];
    const float* Wr_url = (const float*)d_in[18];
    const float* Wctx = (const float*)d_in[19];
    const float* bctx = (const float*)d_in[20];
    const float* Wc1 = (const float*)d_in[21];
    const float* bc1 = (const float*)d_in[22];
    const float* Wc2 = (const float*)d_in[23];
    const float* bc2 = (const float*)d_in[24];
    float* out = (float*)d_out;

    float *mx_pc, *mx_url, *pcH, *urlH;
    float *Wf, *W2pc, *W2url, *A1pc, *A2pc, *A1url, *A2url, *B1pc, *c1pc, *B1url, *c1url, *AU, *cU;
    SYMADDR(mx_pc, g_mx_pc); SYMADDR(mx_url, g_mx_url);
    SYMADDR(pcH, g_pcH); SYMADDR(urlH, g_urlH);
    SYMADDR(Wf, g_Wf); SYMADDR(W2pc, g_W2pc); SYMADDR(W2url, g_W2url);
    SYMADDR(A1pc, g_A1pc); SYMADDR(A2pc, g_A2pc); SYMADDR(A1url, g_A1url); SYMADDR(A2url, g_A2url);
    SYMADDR(B1pc, g_B1pc); SYMADDR(c1pc, g_c1pc); SYMADDR(B1url, g_B1url); SYMADDR(c1url, g_c1url);
    SYMADDR(AU, g_AU); SYMADDR(cU, g_cU);

    int *cnt_ups, *off_ups, *cur_ups, *adj_ups;
    int *cnt_uus, *off_uus, *cur_uus, *adj_uus;
    SYMADDR(cnt_ups, g_cnt_ups); SYMADDR(off_ups, g_off_ups); SYMADDR(cur_ups, g_cur_ups); SYMADDR(adj_ups, g_adj_ups);
    SYMADDR(cnt_uus, g_cnt_uus); SYMADDR(off_uus, g_off_uus); SYMADDR(cur_uus, g_cur_uus); SYMADDR(adj_uus, g_adj_uus);

    const int SAGE_SMEM = (64 * ASTRIDE + 8 * HD * 2 + 4 * HD + 2 * HD + 64 * 8 + 64 * 4) * 4;  // 48128 B
    cudaFuncSetAttribute(sage_fused, cudaFuncAttributeMaxDynamicSharedMemorySize, SAGE_SMEM);

    cudaStream_t s0 = 0;
    cudaStream_t s1 = g_sc.s1, s2 = g_sc.s2, s3 = g_sc.s3;

    // ---- fork ----
    cudaEventRecord(g_sc.evRoot, s0);
    cudaStreamWaitEvent(s1, g_sc.evRoot, 0);
    cudaStreamWaitEvent(s2, g_sc.evRoot, 0);
    cudaStreamWaitEvent(s3, g_sc.evRoot, 0);

    // ---- s3: weight folding ----
    prep_kernel<<<73, 256, 0, s3>>>(Wctx, Wc1, Wu, bu, Wp, bp, Wrf, brf,
                                    Wl_pc, Wr_pc, bl_pc, Wl_url, Wr_url, bl_url,
                                    bctx, bc1,
                                    Wf, W2pc, W2url, A1pc, A2pc, A1url, A2url,
                                    B1pc, c1pc, B1url, c1url, AU, cU);
    cudaEventRecord(g_sc.evPrep, s3);

    // ---- s2: url chain (own accum -> own sage) ----
    cudaMemsetAsync(mx_url, 0, NURL * 8 * sizeof(float), s2);
    accum_kernel<<<(EUU + 255) / 256, 256, 0, s2>>>(x_user, uu_src, uu_dst, EUU, mx_url);
    cudaStreamWaitEvent(s2, g_sc.evPrep, 0);
    sage_fused<<<(NURL + 63) / 64, 256, SAGE_SMEM, s2>>>(x_url, 3, mx_url,
                                                         A1url, B1url, c1url,
                                                         A2url, W2url, bl_url + HD,
                                                         Wf + HD * 64, urlH, NURL);
    cudaEventRecord(g_sc.evURL, s2);

    // ---- s1: pc chain (own accum -> own sage) ----
    cudaMemsetAsync(mx_pc, 0, NPC * 8 * sizeof(float), s1);
    accum_kernel<<<(EUP + 255) / 256, 256, 0, s1>>>(x_user, up_src, up_dst, EUP, mx_pc);
    cudaStreamWaitEvent(s1, g_sc.evPrep, 0);
    sage_fused<<<(NPC + 63) / 64, 256, SAGE_SMEM, s1>>>(x_pc, 4, mx_pc,
                                                        A1pc, B1pc, c1pc,
                                                        A2pc, W2pc, bl_pc + HD,
                                                        Wf, pcH, NPC);
    cudaEventRecord(g_sc.evPC, s1);

    // ---- s0: src-side CSR (overlapped) ----
    cudaMemsetAsync(cnt_ups, 0, NU * sizeof(int), s0);
    cudaMemsetAsync(cnt_uus, 0, NU * sizeof(int), s0);
    count2_kernel<<<(EUP + EUU + 255) / 256, 256, 0, s0>>>(up_src, uu_src, cnt_ups, cnt_uus);
    SetDesc d2{cnt_ups, off_ups, cur_ups, NU};
    SetDesc d3{cnt_uus, off_uus, cur_uus, NU};
    dim3 gScan((NU + 1023) / 1024, 2);
    scanA_kernel<<<gScan, 256, 0, s0>>>(d2, d3);
    scanB_kernel<<<2, 128, 0, s0>>>(d2, d3);
    scanC_kernel<<<gScan, 256, 0, s0>>>(d2, d3);
    fill2_kernel<<<(EUP + EUU + 255) / 256, 256, 0, s0>>>(up_src, up_dst, uu_src, uu_dst,
                                                          cur_ups, adj_ups, cur_uus, adj_uus);

    // ---- join on s0: fused gather + classifier ----
    cudaStreamWaitEvent(s0, g_sc.evPC, 0);
    cudaStreamWaitEvent(s0, g_sc.evURL, 0);
    gather_cls_kernel<<<(NU + 7) / 8, 256, 0, s0>>>(x_user, AU, cU, pcH, urlH,
                                                    off_ups, adj_ups, off_uus, adj_uus,
                                                    Wc2, bc2, out, NU);
}